// round 2
// baseline (speedup 1.0000x reference)
#include <cuda_runtime.h>
#include <math.h>

// Problem constants
#define BATCH 4
#define SEQ   2048
#define DIM   1024
#define HEADS 16
#define KDIM  64
#define TDIM  3072   // 3*DIM

// ---------------------------------------------------------------------------
// Scratch (__device__ globals; allocation-free)
// ---------------------------------------------------------------------------
__device__ float g_qkv[BATCH * SEQ * TDIM];        // 100 MB  [B][L][3D]
__device__ float g_S  [HEADS * SEQ * SEQ];         // 256 MB  per-batch reuse [H][L][M]
__device__ float g_G  [SEQ * SEQ];                 // 16 MB   [L][M]
__device__ float g_att[BATCH * SEQ * DIM];         // 32 MB   [B][L][D] (concatted layout)

// ---------------------------------------------------------------------------
// Generic 128x128x16 fp32 SGEMM: C[M,N] = A[M,K] @ B[K,N]  (all row-major,
// M%128==0, N%128==0, K%16==0 — holds for both projections here)
// ---------------------------------------------------------------------------
__global__ void __launch_bounds__(256) sgemm_kernel(
    const float* __restrict__ A, const float* __restrict__ Bw,
    float* __restrict__ C, int M, int N, int K)
{
    __shared__ float As[16][132];   // transposed A tile [k][m], padded
    __shared__ float Bs[16][132];   // natural B tile [k][n], padded

    const int tid = threadIdx.x;
    const int ty = tid >> 4;        // 0..15
    const int tx = tid & 15;        // 0..15
    const int row0 = blockIdx.y * 128;
    const int col0 = blockIdx.x * 128;

    float acc[8][8];
    #pragma unroll
    for (int i = 0; i < 8; i++)
        #pragma unroll
        for (int j = 0; j < 8; j++) acc[i][j] = 0.0f;

    for (int k0 = 0; k0 < K; k0 += 16) {
        // Load A tile (128 rows x 16 cols), store transposed
        #pragma unroll
        for (int it = 0; it < 2; it++) {
            int f = tid + it * 256;          // 0..511 float4 slots
            int r = f >> 2, c4 = f & 3;
            float4 v = *(const float4*)&A[(size_t)(row0 + r) * K + k0 + c4 * 4];
            As[c4 * 4 + 0][r] = v.x;
            As[c4 * 4 + 1][r] = v.y;
            As[c4 * 4 + 2][r] = v.z;
            As[c4 * 4 + 3][r] = v.w;
        }
        // Load B tile (16 rows x 128 cols), natural
        #pragma unroll
        for (int it = 0; it < 2; it++) {
            int f = tid + it * 256;
            int r = f >> 5, c4 = f & 31;
            *(float4*)&Bs[r][c4 * 4] =
                *(const float4*)&Bw[(size_t)(k0 + r) * N + col0 + c4 * 4];
        }
        __syncthreads();

        #pragma unroll
        for (int k = 0; k < 16; k++) {
            float4 a0 = *(const float4*)&As[k][ty * 8];
            float4 a1 = *(const float4*)&As[k][ty * 8 + 4];
            float4 b0 = *(const float4*)&Bs[k][tx * 8];
            float4 b1 = *(const float4*)&Bs[k][tx * 8 + 4];
            float a[8] = {a0.x, a0.y, a0.z, a0.w, a1.x, a1.y, a1.z, a1.w};
            float b[8] = {b0.x, b0.y, b0.z, b0.w, b1.x, b1.y, b1.z, b1.w};
            #pragma unroll
            for (int i = 0; i < 8; i++)
                #pragma unroll
                for (int j = 0; j < 8; j++)
                    acc[i][j] = fmaf(a[i], b[j], acc[i][j]);
        }
        __syncthreads();
    }

    // Write C
    #pragma unroll
    for (int i = 0; i < 8; i++) {
        float* cp = &C[(size_t)(row0 + ty * 8 + i) * N + col0 + tx * 8];
        float4 o0 = make_float4(acc[i][0], acc[i][1], acc[i][2], acc[i][3]);
        float4 o1 = make_float4(acc[i][4], acc[i][5], acc[i][6], acc[i][7]);
        *(float4*)&cp[0] = o0;
        *(float4*)&cp[4] = o1;
    }
}

// ---------------------------------------------------------------------------
// Reshape-without-transpose addressing:
//   qh[b,h,l,k] lives at g_qkv[b][ h*128 + (l>>4) ][ (l&15)*64 + k  + seg*1024 ]
// (the [L,D] q/k/v slab reinterpreted as [H,L,K]); each (h,l) row is 64
// contiguous floats.
// ---------------------------------------------------------------------------
__device__ __forceinline__ const float* head_row(const float* base_b, int h, int l, int seg)
{
    return base_b + (size_t)(h * 128 + (l >> 4)) * TDIM + ((l & 15) * 64) + seg * 1024;
}

// ---------------------------------------------------------------------------
// Scores: S[h][l][m] = (1/8) * dot64(qh[l], kh[m])   for one batch b
// grid (32 m-tiles, 32 l-tiles, 16 heads), block 256
// ---------------------------------------------------------------------------
__global__ void __launch_bounds__(256) scores_kernel(int b)
{
    __shared__ float Qst[64][68];   // [k][l]
    __shared__ float Kst[64][68];   // [k][m]

    const int tid = threadIdx.x;
    const int h = blockIdx.z;
    const int l0 = blockIdx.y * 64;
    const int m0 = blockIdx.x * 64;
    const float* base = g_qkv + (size_t)b * SEQ * TDIM;

    {
        const int lr = tid >> 2;                         // local row 0..63
        const float* qrow = head_row(base, h, l0 + lr, 0);
        const float* krow = head_row(base, h, m0 + lr, 1);
        #pragma unroll
        for (int i = 0; i < 4; i++) {
            int j = (tid & 3) + 4 * i;                   // float4 idx 0..15
            float4 v = *(const float4*)&qrow[j * 4];
            Qst[j * 4 + 0][lr] = v.x;
            Qst[j * 4 + 1][lr] = v.y;
            Qst[j * 4 + 2][lr] = v.z;
            Qst[j * 4 + 3][lr] = v.w;
            float4 w = *(const float4*)&krow[j * 4];
            Kst[j * 4 + 0][lr] = w.x;
            Kst[j * 4 + 1][lr] = w.y;
            Kst[j * 4 + 2][lr] = w.z;
            Kst[j * 4 + 3][lr] = w.w;
        }
    }
    __syncthreads();

    const int ty = tid >> 4, tx = tid & 15;
    float acc[4][4];
    #pragma unroll
    for (int i = 0; i < 4; i++)
        #pragma unroll
        for (int j = 0; j < 4; j++) acc[i][j] = 0.0f;

    #pragma unroll 8
    for (int k = 0; k < 64; k++) {
        float4 a  = *(const float4*)&Qst[k][ty * 4];
        float4 bb = *(const float4*)&Kst[k][tx * 4];
        float av[4] = {a.x, a.y, a.z, a.w};
        float bv[4] = {bb.x, bb.y, bb.z, bb.w};
        #pragma unroll
        for (int i = 0; i < 4; i++)
            #pragma unroll
            for (int j = 0; j < 4; j++)
                acc[i][j] = fmaf(av[i], bv[j], acc[i][j]);
    }

    float* Sp = g_S + (size_t)h * SEQ * SEQ;
    #pragma unroll
    for (int i = 0; i < 4; i++) {
        float4 o = make_float4(acc[i][0] * 0.125f, acc[i][1] * 0.125f,
                               acc[i][2] * 0.125f, acc[i][3] * 0.125f);
        *(float4*)&Sp[(size_t)(l0 + ty * 4 + i) * SEQ + m0 + tx * 4] = o;
    }
}

// ---------------------------------------------------------------------------
// Softmax-over-heads stats: G[l,m] = exp(-max_h s) / sum_h exp(s - max_h)
// so that P[h,l,m] = exp(s[h,l,m]) * G[l,m]
// ---------------------------------------------------------------------------
__global__ void __launch_bounds__(256) stats_kernel()
{
    const size_t lm = (size_t)blockIdx.x * 256 + threadIdx.x;
    float s[HEADS];
    #pragma unroll
    for (int h = 0; h < HEADS; h++)
        s[h] = g_S[(size_t)h * SEQ * SEQ + lm];
    float mx = s[0];
    #pragma unroll
    for (int h = 1; h < HEADS; h++) mx = fmaxf(mx, s[h]);
    float z = 0.0f;
    #pragma unroll
    for (int h = 0; h < HEADS; h++) z += __expf(s[h] - mx);
    g_G[lm] = __expf(-mx) / z;
}

// ---------------------------------------------------------------------------
// PV: att[l, h*64+k] = sum_m ( exp(S[h,l,m]) * G[l,m] ) * vh[m,k]
// grid (1, 32 l-tiles, 16 heads), block 256; loops m in 64-chunks
// ---------------------------------------------------------------------------
__global__ void __launch_bounds__(256) pv_kernel(int b)
{
    __shared__ float Pst[64][68];   // [m][l]
    __shared__ float Vs [64][68];   // [m][k]

    const int tid = threadIdx.x;
    const int h = blockIdx.z;
    const int l0 = blockIdx.y * 64;
    const float* base = g_qkv + (size_t)b * SEQ * TDIM;
    const float* Sp = g_S + (size_t)h * SEQ * SEQ;

    const int ty = tid >> 4, tx = tid & 15;
    const int lr = tid >> 2;
    float acc[4][4];
    #pragma unroll
    for (int i = 0; i < 4; i++)
        #pragma unroll
        for (int j = 0; j < 4; j++) acc[i][j] = 0.0f;

    for (int m0 = 0; m0 < SEQ; m0 += 64) {
        const float* srow = Sp  + (size_t)(l0 + lr) * SEQ + m0;
        const float* grow = g_G + (size_t)(l0 + lr) * SEQ + m0;
        const float* vrow = head_row(base, h, m0 + lr, 2);
        #pragma unroll
        for (int i = 0; i < 4; i++) {
            int j = (tid & 3) + 4 * i;
            float4 s = *(const float4*)&srow[j * 4];
            float4 g = *(const float4*)&grow[j * 4];
            Pst[j * 4 + 0][lr] = __expf(s.x) * g.x;
            Pst[j * 4 + 1][lr] = __expf(s.y) * g.y;
            Pst[j * 4 + 2][lr] = __expf(s.z) * g.z;
            Pst[j * 4 + 3][lr] = __expf(s.w) * g.w;
            *(float4*)&Vs[lr][j * 4] = *(const float4*)&vrow[j * 4];
        }
        __syncthreads();

        #pragma unroll 8
        for (int m = 0; m < 64; m++) {
            float4 a  = *(const float4*)&Pst[m][ty * 4];
            float4 bb = *(const float4*)&Vs[m][tx * 4];
            float av[4] = {a.x, a.y, a.z, a.w};
            float bv[4] = {bb.x, bb.y, bb.z, bb.w};
            #pragma unroll
            for (int i = 0; i < 4; i++)
                #pragma unroll
                for (int j = 0; j < 4; j++)
                    acc[i][j] = fmaf(av[i], bv[j], acc[i][j]);
        }
        __syncthreads();
    }

    // Write into concatted layout [B][L][D], columns h*64 + ...
    #pragma unroll
    for (int i = 0; i < 4; i++) {
        float* ap = &g_att[(size_t)((b * SEQ) + l0 + ty * 4 + i) * DIM + h * 64 + tx * 4];
        *(float4*)ap = make_float4(acc[i][0], acc[i][1], acc[i][2], acc[i][3]);
    }
}

// ---------------------------------------------------------------------------
// Launch
// ---------------------------------------------------------------------------
extern "C" void kernel_launch(void* const* d_in, const int* in_sizes, int n_in,
                              void* d_out, int out_size)
{
    const float* x    = (const float*)d_in[0];   // [4, 2048, 1024]
    const float* wqkv = (const float*)d_in[1];   // [1024, 3072]
    const float* wo   = (const float*)d_in[2];   // [1024, 1024]
    float* out = (float*)d_out;                  // [4, 2048, 1024]

    float* qkv;  cudaGetSymbolAddress((void**)&qkv,  g_qkv);
    float* att;  cudaGetSymbolAddress((void**)&att,  g_att);

    // 1. QKV projection: [8192,1024] @ [1024,3072]
    {
        dim3 grid(TDIM / 128, (BATCH * SEQ) / 128);
        sgemm_kernel<<<grid, 256>>>(x, wqkv, qkv, BATCH * SEQ, TDIM, DIM);
    }

    // 2. Per-batch attention (S buffer reused; stream ordering serializes)
    for (int b = 0; b < BATCH; b++) {
        {
            dim3 grid(SEQ / 64, SEQ / 64, HEADS);
            scores_kernel<<<grid, 256>>>(b);
        }
        stats_kernel<<<(SEQ * SEQ) / 256, 256>>>();
        {
            dim3 grid(1, SEQ / 64, HEADS);
            pv_kernel<<<grid, 256>>>(b);
        }
    }

    // 3. Output projection: [8192,1024] @ [1024,1024]
    {
        dim3 grid(DIM / 128, (BATCH * SEQ) / 128);
        sgemm_kernel<<<grid, 256>>>(att, wo, out, BATCH * SEQ, DIM, DIM);
    }
}

// round 10
// speedup vs baseline: 1.7229x; 1.7229x over previous
#include <cuda_runtime.h>
#include <cuda_bf16.h>
#include <stdint.h>

#define BATCH 4
#define SEQ   2048
#define DIM   1024
#define HEADS 16
#define TDIM  3072

// tcgen05 is arch-specific ('a'/'f' feature): only emit it in compilation
// passes that have it (sm_103a / sm_100a / family-specific). The plain
// compute_103 PTX pass gets a correct FFMA fallback instead.
#if !defined(__CUDA_ARCH__)
#define TC_OK 0   /* host pass: value unused in device code */
#elif defined(__CUDA_ARCH_FEAT_SM103_ALL) || defined(__CUDA_ARCH_FEAT_SM100_ALL) || \
      defined(__CUDA_ARCH_SPECIFIC__) || defined(__CUDA_ARCH_FAMILY_SPECIFIC__)
#define TC_OK 1
#else
#define TC_OK 0
#endif

// ---------------- scratch ----------------
__device__ __align__(256) float g_qkv[BATCH * SEQ * TDIM];
__device__ __align__(256) float g_S[(size_t)HEADS * SEQ * SEQ];   // per-batch reuse
__device__ __align__(256) float g_G[SEQ * SEQ];
__device__ __align__(256) __nv_bfloat16 g_xh[BATCH * SEQ * DIM];
__device__ __align__(256) __nv_bfloat16 g_xl[BATCH * SEQ * DIM];
__device__ __align__(256) __nv_bfloat16 g_wqh[TDIM * DIM];
__device__ __align__(256) __nv_bfloat16 g_wql[TDIM * DIM];
__device__ __align__(256) __nv_bfloat16 g_woh[DIM * DIM];
__device__ __align__(256) __nv_bfloat16 g_wol[DIM * DIM];
__device__ __align__(256) __nv_bfloat16 g_qhh[BATCH * HEADS * SEQ * 64];
__device__ __align__(256) __nv_bfloat16 g_qhl[BATCH * HEADS * SEQ * 64];
__device__ __align__(256) __nv_bfloat16 g_khh[BATCH * HEADS * SEQ * 64];
__device__ __align__(256) __nv_bfloat16 g_khl[BATCH * HEADS * SEQ * 64];
__device__ __align__(256) __nv_bfloat16 g_vth[BATCH * HEADS * 64 * SEQ];
__device__ __align__(256) __nv_bfloat16 g_vtl[BATCH * HEADS * 64 * SEQ];
__device__ __align__(256) __nv_bfloat16 g_ath[BATCH * SEQ * DIM];
__device__ __align__(256) __nv_bfloat16 g_atl[BATCH * SEQ * DIM];

// ---------------- PTX helpers ----------------
__device__ __forceinline__ uint32_t smem_u32(const void* p) {
    return (uint32_t)__cvta_generic_to_shared(p);
}
__device__ __forceinline__ uint32_t elect_one() {
    uint32_t pred;
    asm volatile("{\n\t.reg .pred p;\n\telect.sync _|p, 0xFFFFFFFF;\n\tselp.b32 %0, 1, 0, p;\n\t}"
                 : "=r"(pred));
    return pred;
}
#define MBAR_INIT(a, c) \
    asm volatile("mbarrier.init.shared.b64 [%0], %1;" :: "r"(a), "r"(c) : "memory")
#define MBAR_WAIT(addr, par) do {                                               \
    uint32_t _m = (addr), _p = (par), _d;                                       \
    asm volatile("{\n\t.reg .pred p;\n\t"                                       \
        "mbarrier.try_wait.parity.acquire.cta.shared::cta.b64 p, [%1], %2;\n\t" \
        "selp.b32 %0, 1, 0, p;\n\t}" : "=r"(_d) : "r"(_m), "r"(_p) : "memory"); \
    if (!_d) {                                                                  \
        asm volatile("{\n\t.reg .pred P1;\n\t"                                  \
        "WL_%=:\n\t"                                                            \
        "mbarrier.try_wait.parity.acquire.cta.shared::cta.b64 P1, [%0], %1, 0x989680;\n\t" \
        "@P1 bra.uni WD_%=;\n\tbra.uni WL_%=;\n\tWD_%=:\n\t}"                   \
        :: "r"(_m), "r"(_p) : "memory");                                        \
    }                                                                           \
} while (0)
#define TC_ALLOC(sa, n) \
    asm volatile("tcgen05.alloc.cta_group::1.sync.aligned.shared::cta.b32 [%0], %1;" :: "r"(sa), "r"(n) : "memory")
#define TC_DEALLOC(t, n) \
    asm volatile("tcgen05.dealloc.cta_group::1.sync.aligned.b32 %0, %1;" :: "r"(t), "r"(n))
#define TC_RELINQ() \
    asm volatile("tcgen05.relinquish_alloc_permit.cta_group::1.sync.aligned;")
#define TC_COMMIT(a) \
    asm volatile("tcgen05.commit.cta_group::1.mbarrier::arrive::one.shared::cluster.b64 [%0];" :: "r"(a) : "memory")
#define TC_FENCE_AFTER()  asm volatile("tcgen05.fence::after_thread_sync;" ::: "memory")
#define TC_WAIT_LD()      asm volatile("tcgen05.wait::ld.sync.aligned;" ::: "memory")
#define FENCE_ASYNC()     asm volatile("fence.proxy.async.shared::cta;" ::: "memory")

#define TC_LD_X32(r, a) \
    asm volatile( \
        "tcgen05.ld.sync.aligned.32x32b.x32.b32 " \
        "{%0, %1, %2, %3, %4, %5, %6, %7, %8, %9, %10, %11, %12, %13, %14, %15, " \
        " %16, %17, %18, %19, %20, %21, %22, %23, %24, %25, %26, %27, %28, %29, %30, %31}, [%32];" \
        : "=r"((r)[0]),  "=r"((r)[1]),  "=r"((r)[2]),  "=r"((r)[3]), \
          "=r"((r)[4]),  "=r"((r)[5]),  "=r"((r)[6]),  "=r"((r)[7]), \
          "=r"((r)[8]),  "=r"((r)[9]),  "=r"((r)[10]), "=r"((r)[11]), \
          "=r"((r)[12]), "=r"((r)[13]), "=r"((r)[14]), "=r"((r)[15]), \
          "=r"((r)[16]), "=r"((r)[17]), "=r"((r)[18]), "=r"((r)[19]), \
          "=r"((r)[20]), "=r"((r)[21]), "=r"((r)[22]), "=r"((r)[23]), \
          "=r"((r)[24]), "=r"((r)[25]), "=r"((r)[26]), "=r"((r)[27]), \
          "=r"((r)[28]), "=r"((r)[29]), "=r"((r)[30]), "=r"((r)[31]) \
        : "r"(a))

#define SWZ(x) ((x) ^ (((x) >> 3) & 0x70))

__device__ __forceinline__ uint64_t make_desc(uint32_t addr) {
    const uint64_t base =
        (uint64_t(2) << 61) | (uint64_t(1) << 46) | (uint64_t(64) << 32) | (uint64_t(1) << 16);
    return base | ((addr >> 4) & 0x3FFF);
}
#if defined(__CUDA_ARCH__)
#if TC_OK
__device__ __forceinline__ void mma_bf16(uint32_t d, uint64_t ad, uint64_t bd,
                                         uint32_t idesc, uint32_t en) {
    asm volatile(
        "{\n\t.reg .pred p;\n\tsetp.ne.u32 p, %5, 0;\n\t"
        "tcgen05.mma.cta_group::1.kind::f16 [%0], %1, %2, %3, {%4, %4, %4, %4}, p;\n\t}"
        :: "r"(d), "l"(ad), "l"(bd), "r"(idesc), "r"(0u), "r"(en) : "memory");
}
#endif
#endif

// hi/lo bf16 split of a float4 -> two packed uint2 (4 bf16 each)
__device__ __forceinline__ void split4(float4 p, uint2& hv, uint2& lv) {
    __nv_bfloat16 h0 = __float2bfloat16(p.x), h1 = __float2bfloat16(p.y);
    __nv_bfloat16 h2 = __float2bfloat16(p.z), h3 = __float2bfloat16(p.w);
    __nv_bfloat16 l0 = __float2bfloat16(p.x - __bfloat162float(h0));
    __nv_bfloat16 l1 = __float2bfloat16(p.y - __bfloat162float(h1));
    __nv_bfloat16 l2 = __float2bfloat16(p.z - __bfloat162float(h2));
    __nv_bfloat16 l3 = __float2bfloat16(p.w - __bfloat162float(h3));
    __nv_bfloat162 a, b, c, d;
    a.x = h0; a.y = h1; b.x = h2; b.y = h3;
    c.x = l0; c.y = l1; d.x = l2; d.y = l3;
    hv.x = *(uint32_t*)&a; hv.y = *(uint32_t*)&b;
    lv.x = *(uint32_t*)&c; lv.y = *(uint32_t*)&d;
}

// ---------------- conversion kernels ----------------
__global__ void __launch_bounds__(256) split_kernel(const float4* __restrict__ src,
                                                    __nv_bfloat16* __restrict__ hi,
                                                    __nv_bfloat16* __restrict__ lo, int n4) {
    int i = blockIdx.x * 256 + threadIdx.x;
    if (i >= n4) return;
    uint2 hv, lv;
    split4(src[i], hv, lv);
    *(uint2*)(hi + (size_t)i * 4) = hv;
    *(uint2*)(lo + (size_t)i * 4) = lv;
}

// T[n][k] = W[k][n], split hi/lo
__global__ void __launch_bounds__(256) transpose_split_kernel(
    const float* __restrict__ W, __nv_bfloat16* __restrict__ Th,
    __nv_bfloat16* __restrict__ Tl, int K, int N) {
    __shared__ float t[32][33];
    const int n0 = blockIdx.x * 32, k0 = blockIdx.y * 32;
    const int tx = threadIdx.x, ty = threadIdx.y;
    #pragma unroll
    for (int j = 0; j < 32; j += 8)
        t[ty + j][tx] = W[(size_t)(k0 + ty + j) * N + n0 + tx];
    __syncthreads();
    #pragma unroll
    for (int j = 0; j < 32; j += 8) {
        float v = t[tx][ty + j];
        size_t o = (size_t)(n0 + ty + j) * K + k0 + tx;
        __nv_bfloat16 h = __float2bfloat16(v);
        Th[o] = h;
        Tl[o] = __float2bfloat16(v - __bfloat162float(h));
    }
}

// q/k head extraction: dst[((b*16+h)*2048+l)*64 + k] from g_qkv (reshape quirk)
__global__ void __launch_bounds__(256) conv_qk_kernel() {
    int i4 = blockIdx.x * 256 + threadIdx.x;   // < 2^21, one float4 each
    int k4 = i4 & 15;
    int l  = (i4 >> 4) & 2047;
    int h  = (i4 >> 15) & 15;
    int b  = i4 >> 19;
    const float* row = g_qkv + (size_t)b * SEQ * TDIM
                     + (size_t)(h * 128 + (l >> 4)) * TDIM + (l & 15) * 64 + k4 * 4;
    size_t o = (size_t)i4 * 4;
    uint2 hv, lv;
    split4(*(const float4*)row, hv, lv);
    *(uint2*)(g_qhh + o) = hv; *(uint2*)(g_qhl + o) = lv;
    split4(*(const float4*)(row + 1024), hv, lv);
    *(uint2*)(g_khh + o) = hv; *(uint2*)(g_khl + o) = lv;
}

// v transposed per (b,h): vt[64 k][2048 m]
__global__ void __launch_bounds__(256) conv_vt_kernel() {
    __shared__ float t[64][65];
    const int z = blockIdx.y;                    // b*16+h
    const int b = z >> 4, h = z & 15;
    const int m0 = blockIdx.x * 64;
    const int tid = threadIdx.x;
    for (int idx = tid; idx < 1024; idx += 256) {
        int r = idx >> 4, c4 = idx & 15;
        int m = m0 + r;
        const float* row = g_qkv + (size_t)b * SEQ * TDIM
                         + (size_t)(h * 128 + (m >> 4)) * TDIM + (m & 15) * 64 + 2048 + c4 * 4;
        float4 v = *(const float4*)row;
        t[r][c4 * 4 + 0] = v.x; t[r][c4 * 4 + 1] = v.y;
        t[r][c4 * 4 + 2] = v.z; t[r][c4 * 4 + 3] = v.w;
    }
    __syncthreads();
    for (int idx = tid; idx < 1024; idx += 256) {
        int kk = idx >> 4, c4 = idx & 15;
        float4 v;
        v.x = t[c4 * 4 + 0][kk]; v.y = t[c4 * 4 + 1][kk];
        v.z = t[c4 * 4 + 2][kk]; v.w = t[c4 * 4 + 3][kk];
        size_t o = ((size_t)z * 64 + kk) * SEQ + m0 + c4 * 4;
        uint2 hv, lv;
        split4(v, hv, lv);
        *(uint2*)(g_vth + o) = hv;
        *(uint2*)(g_vtl + o) = lv;
    }
}

// ---------------- generic tcgen05 bf16x3 GEMM (128x128 tile, K%64==0) ----------------
// C[128,128] = scale * A[128,K] @ B[128,K]^T ; A/B row-major K-major hi/lo bf16
__global__ void __launch_bounds__(256, 1) gemm_tc(
    const __nv_bfloat16* __restrict__ Ah, const __nv_bfloat16* __restrict__ Al,
    const __nv_bfloat16* __restrict__ Bh, const __nv_bfloat16* __restrict__ Bl,
    float* __restrict__ C, int K, int ldA, int ldB, int ldC,
    long long sAz, long long sBz, long long sCz, float scale)
{
    extern __shared__ char dsm[];
    uint32_t raw = smem_u32(dsm);
    uint32_t sbase = (raw + 1023) & ~1023u;
    char* sp = dsm + (sbase - raw);
    const int tid = threadIdx.x, wid = tid >> 5, lid = tid & 31;
    const int z = blockIdx.z;
    const int row0 = blockIdx.y * 128, col0 = blockIdx.x * 128;
    Ah += (size_t)z * sAz; Al += (size_t)z * sAz;
    Bh += (size_t)z * sBz; Bl += (size_t)z * sBz;
    C  += (size_t)z * sCz;
#if TC_OK
    const uint32_t MB0 = sbase + 8, MB1 = sbase + 16;
    const int STAGE = 65536;                 // Ah,Al,Bh,Bl x 16KB

    if (wid == 0) {
        if (elect_one()) { MBAR_INIT(MB0, 1); MBAR_INIT(MB1, 1); }
        TC_ALLOC(sbase, 128);
        TC_RELINQ();
    }
    __syncthreads();
    uint32_t tmem;
    asm volatile("ld.shared.b32 %0, [%1];" : "=r"(tmem) : "r"(sbase));

    const uint32_t IDESC = (1u << 4) | (1u << 7) | (1u << 10) | (16u << 17) | (8u << 24);
    const int T = K >> 6;
    uint32_t ph0 = 0, ph1 = 0;
    for (int t = 0; t < T; ++t) {
        const int buf = t & 1;
        if (t >= 2) {
            if (!buf) { MBAR_WAIT(MB0, ph0); ph0 ^= 1; }
            else      { MBAR_WAIT(MB1, ph1); ph1 ^= 1; }
        }
        char* S0 = sp + 1024 + buf * STAGE;
        const int k0 = t * 64;
        for (int idx = tid; idx < 1024; idx += 256) {
            int r = idx >> 3, c = idx & 7;
            size_t ao = (size_t)(row0 + r) * ldA + k0 + c * 8;
            size_t bo = (size_t)(col0 + r) * ldB + k0 + c * 8;
            uint32_t off = SWZ(r * 128 + c * 16);
            *(uint4*)(S0 + off)         = *(const uint4*)(Ah + ao);
            *(uint4*)(S0 + 16384 + off) = *(const uint4*)(Al + ao);
            *(uint4*)(S0 + 32768 + off) = *(const uint4*)(Bh + bo);
            *(uint4*)(S0 + 49152 + off) = *(const uint4*)(Bl + bo);
        }
        __syncthreads();
        if (wid == 0) {
            FENCE_ASYNC();
            if (elect_one()) {
                uint32_t sb = sbase + 1024 + buf * STAGE;
                uint64_t dah = make_desc(sb), dal = make_desc(sb + 16384);
                uint64_t dbh = make_desc(sb + 32768), dbl = make_desc(sb + 49152);
                #pragma unroll
                for (int ks = 0; ks < 4; ++ks) {
                    mma_bf16(tmem, dah + ks * 2, dbh + ks * 2, IDESC, (uint32_t)((t | ks) != 0));
                    mma_bf16(tmem, dah + ks * 2, dbl + ks * 2, IDESC, 1u);
                    mma_bf16(tmem, dal + ks * 2, dbh + ks * 2, IDESC, 1u);
                }
                TC_COMMIT(buf ? MB1 : MB0);
            }
        }
    }
    for (int r = (T >= 2 ? T - 2 : 0); r < T; ++r) {
        if (!(r & 1)) { MBAR_WAIT(MB0, ph0); ph0 ^= 1; }
        else          { MBAR_WAIT(MB1, ph1); ph1 ^= 1; }
    }
    TC_FENCE_AFTER();
    if (wid < 4) {
        const int row = row0 + wid * 32 + lid;
        float* cp = C + (size_t)row * ldC + col0;
        for (int c0 = 0; c0 < 128; c0 += 32) {
            uint32_t r[32];
            TC_LD_X32(r, tmem + c0);
            TC_WAIT_LD();
            #pragma unroll
            for (int j = 0; j < 32; j += 4) {
                float4 o;
                o.x = __uint_as_float(r[j + 0]) * scale;
                o.y = __uint_as_float(r[j + 1]) * scale;
                o.z = __uint_as_float(r[j + 2]) * scale;
                o.w = __uint_as_float(r[j + 3]) * scale;
                *(float4*)&cp[c0 + j] = o;
            }
        }
    }
    __syncthreads();
    if (wid == 0) TC_DEALLOC(tmem, 128);
#else
    // FFMA fallback (compute_103 PTX pass only; correct but slow)
    float* As = (float*)sp;                  // [16][132]
    float* Bs = As + 16 * 132;               // [16][132]
    const int ty = tid >> 4, tx = tid & 15;
    float acc[8][8];
    #pragma unroll
    for (int i = 0; i < 8; i++)
        #pragma unroll
        for (int j = 0; j < 8; j++) acc[i][j] = 0.0f;
    for (int k0 = 0; k0 < K; k0 += 16) {
        for (int idx = tid; idx < 2048; idx += 256) {
            int r = idx >> 4, c = idx & 15;
            size_t ao = (size_t)(row0 + r) * ldA + k0 + c;
            size_t bo = (size_t)(col0 + r) * ldB + k0 + c;
            As[c * 132 + r] = __bfloat162float(Ah[ao]) + __bfloat162float(Al[ao]);
            Bs[c * 132 + r] = __bfloat162float(Bh[bo]) + __bfloat162float(Bl[bo]);
        }
        __syncthreads();
        #pragma unroll
        for (int k = 0; k < 16; k++) {
            float a[8], bb[8];
            #pragma unroll
            for (int i = 0; i < 8; i++) a[i]  = As[k * 132 + ty * 8 + i];
            #pragma unroll
            for (int j = 0; j < 8; j++) bb[j] = Bs[k * 132 + tx * 8 + j];
            #pragma unroll
            for (int i = 0; i < 8; i++)
                #pragma unroll
                for (int j = 0; j < 8; j++)
                    acc[i][j] = fmaf(a[i], bb[j], acc[i][j]);
        }
        __syncthreads();
    }
    #pragma unroll
    for (int i = 0; i < 8; i++)
        #pragma unroll
        for (int j = 0; j < 8; j++)
            C[(size_t)(row0 + ty * 8 + i) * ldC + col0 + tx * 8 + j] = acc[i][j] * scale;
#endif
}

// ---------------- softmax-over-heads stats ----------------
__global__ void __launch_bounds__(256) stats_kernel() {
    const size_t lm = (size_t)blockIdx.x * 256 + threadIdx.x;
    float s[HEADS];
    #pragma unroll
    for (int h = 0; h < HEADS; h++) s[h] = g_S[(size_t)h * SEQ * SEQ + lm];
    float mx = s[0];
    #pragma unroll
    for (int h = 1; h < HEADS; h++) mx = fmaxf(mx, s[h]);
    float zz = 0.0f;
    #pragma unroll
    for (int h = 0; h < HEADS; h++) zz += __expf(s[h] - mx);
    g_G[lm] = __expf(-mx) / zz;
}

// ---------------- PV: fused exp + bf16x3 MMA, att -> bf16 hi/lo ----------------
__global__ void __launch_bounds__(256, 1) pv_tc(int b)
{
    extern __shared__ char dsm[];
    uint32_t raw = smem_u32(dsm);
    uint32_t sbase = (raw + 1023) & ~1023u;
    char* sp = dsm + (sbase - raw);
    const int tid = threadIdx.x, wid = tid >> 5, lid = tid & 31;
    const int h = blockIdx.y, l0 = blockIdx.x * 128;
    const float* Sp = g_S + (size_t)h * SEQ * SEQ;
    const __nv_bfloat16* Vhp = g_vth + (size_t)((b * HEADS + h) * 64) * SEQ;
    const __nv_bfloat16* Vlp = g_vtl + (size_t)((b * HEADS + h) * 64) * SEQ;
#if TC_OK
    const uint32_t MB0 = sbase + 8, MB1 = sbase + 16;
    const int STAGE = 49152;                 // Ph 16K, Pl 16K, Vh 8K, Vl 8K

    if (wid == 0) {
        if (elect_one()) { MBAR_INIT(MB0, 1); MBAR_INIT(MB1, 1); }
        TC_ALLOC(sbase, 64);
        TC_RELINQ();
    }
    __syncthreads();
    uint32_t tmem;
    asm volatile("ld.shared.b32 %0, [%1];" : "=r"(tmem) : "r"(sbase));

    const uint32_t IDESC = (1u << 4) | (1u << 7) | (1u << 10) | (8u << 17) | (8u << 24);
    uint32_t ph0 = 0, ph1 = 0;
    const int pr = tid >> 1, pc0 = (tid & 1) * 32;
    for (int t = 0; t < 32; ++t) {
        const int buf = t & 1;
        if (t >= 2) {
            if (!buf) { MBAR_WAIT(MB0, ph0); ph0 ^= 1; }
            else      { MBAR_WAIT(MB1, ph1); ph1 ^= 1; }
        }
        char* S0 = sp + 1024 + buf * STAGE;
        const int m0 = t * 64;
        const float* srow = Sp  + (size_t)(l0 + pr) * SEQ + m0 + pc0;
        const float* grow = g_G + (size_t)(l0 + pr) * SEQ + m0 + pc0;
        #pragma unroll
        for (int i = 0; i < 8; ++i) {
            float4 s = *(const float4*)(srow + i * 4);
            float4 g = *(const float4*)(grow + i * 4);
            float4 p;
            p.x = __expf(s.x) * g.x; p.y = __expf(s.y) * g.y;
            p.z = __expf(s.z) * g.z; p.w = __expf(s.w) * g.w;
            uint2 hv, lv;
            split4(p, hv, lv);
            uint32_t off = SWZ(pr * 128 + (pc0 + i * 4) * 2);
            *(uint2*)(S0 + off)         = hv;
            *(uint2*)(S0 + 16384 + off) = lv;
        }
        #pragma unroll
        for (int it = 0; it < 2; ++it) {
            int idx = tid + it * 256;        // 0..511: 64 rows x 8 chunks
            int r = idx >> 3, c = idx & 7;
            size_t vo = (size_t)r * SEQ + m0 + c * 8;
            uint32_t off = SWZ(r * 128 + c * 16);
            *(uint4*)(S0 + 32768 + off) = *(const uint4*)(Vhp + vo);
            *(uint4*)(S0 + 40960 + off) = *(const uint4*)(Vlp + vo);
        }
        __syncthreads();
        if (wid == 0) {
            FENCE_ASYNC();
            if (elect_one()) {
                uint32_t sb = sbase + 1024 + buf * STAGE;
                uint64_t dph = make_desc(sb), dpl = make_desc(sb + 16384);
                uint64_t dvh = make_desc(sb + 32768), dvl = make_desc(sb + 40960);
                #pragma unroll
                for (int ks = 0; ks < 4; ++ks) {
                    mma_bf16(tmem, dph + ks * 2, dvh + ks * 2, IDESC, (uint32_t)((t | ks) != 0));
                    mma_bf16(tmem, dph + ks * 2, dvl + ks * 2, IDESC, 1u);
                    mma_bf16(tmem, dpl + ks * 2, dvh + ks * 2, IDESC, 1u);
                }
                TC_COMMIT(buf ? MB1 : MB0);
            }
        }
    }
    MBAR_WAIT(MB0, ph0);
    MBAR_WAIT(MB1, ph1);
    TC_FENCE_AFTER();
    if (wid < 4) {
        const int row = l0 + wid * 32 + lid;
        __nv_bfloat16* oh = g_ath + (size_t)(b * SEQ + row) * DIM + h * 64;
        __nv_bfloat16* ol = g_atl + (size_t)(b * SEQ + row) * DIM + h * 64;
        for (int c0 = 0; c0 < 64; c0 += 32) {
            uint32_t r[32];
            TC_LD_X32(r, tmem + c0);
            TC_WAIT_LD();
            #pragma unroll
            for (int j = 0; j < 32; j += 4) {
                float4 v;
                v.x = __uint_as_float(r[j + 0]); v.y = __uint_as_float(r[j + 1]);
                v.z = __uint_as_float(r[j + 2]); v.w = __uint_as_float(r[j + 3]);
                uint2 hv, lv;
                split4(v, hv, lv);
                *(uint2*)(oh + c0 + j) = hv;
                *(uint2*)(ol + c0 + j) = lv;
            }
        }
    }
    __syncthreads();
    if (wid == 0) TC_DEALLOC(tmem, 64);
#else
    // FFMA fallback (compute_103 PTX pass only; correct but slow)
    float* Ps = (float*)sp;                  // [16][132]  P[m][l]
    float* Vs = Ps + 16 * 132;               // [16][72]   V[m][k]
    const int ty = tid >> 3;                 // 0..31 -> 4 rows each
    const int tx = tid & 7;                  // 0..7  -> 8 cols each
    float acc[4][8];
    #pragma unroll
    for (int i = 0; i < 4; i++)
        #pragma unroll
        for (int j = 0; j < 8; j++) acc[i][j] = 0.0f;
    for (int m0 = 0; m0 < SEQ; m0 += 16) {
        for (int idx = tid; idx < 2048; idx += 256) {
            int m = idx >> 7, l = idx & 127;
            float s = Sp[(size_t)(l0 + l) * SEQ + m0 + m];
            Ps[m * 132 + l] = __expf(s) * g_G[(size_t)(l0 + l) * SEQ + m0 + m];
        }
        for (int idx = tid; idx < 1024; idx += 256) {
            int m = idx >> 6, k = idx & 63;
            size_t vo = (size_t)k * SEQ + m0 + m;
            Vs[m * 72 + k] = __bfloat162float(Vhp[vo]) + __bfloat162float(Vlp[vo]);
        }
        __syncthreads();
        #pragma unroll
        for (int m = 0; m < 16; m++) {
            float a[4], bb[8];
            #pragma unroll
            for (int i = 0; i < 4; i++) a[i]  = Ps[m * 132 + ty * 4 + i];
            #pragma unroll
            for (int j = 0; j < 8; j++) bb[j] = Vs[m * 72 + tx * 8 + j];
            #pragma unroll
            for (int i = 0; i < 4; i++)
                #pragma unroll
                for (int j = 0; j < 8; j++)
                    acc[i][j] = fmaf(a[i], bb[j], acc[i][j]);
        }
        __syncthreads();
    }
    #pragma unroll
    for (int i = 0; i < 4; i++) {
        int row = l0 + ty * 4 + i;
        __nv_bfloat16* oh = g_ath + (size_t)(b * SEQ + row) * DIM + h * 64 + tx * 8;
        __nv_bfloat16* ol = g_atl + (size_t)(b * SEQ + row) * DIM + h * 64 + tx * 8;
        float4 v0 = make_float4(acc[i][0], acc[i][1], acc[i][2], acc[i][3]);
        float4 v1 = make_float4(acc[i][4], acc[i][5], acc[i][6], acc[i][7]);
        uint2 hv, lv;
        split4(v0, hv, lv);
        *(uint2*)oh = hv; *(uint2*)ol = lv;
        split4(v1, hv, lv);
        *(uint2*)(oh + 4) = hv; *(uint2*)(ol + 4) = lv;
    }
#endif
}

// ---------------- launch ----------------
extern "C" void kernel_launch(void* const* d_in, const int* in_sizes, int n_in,
                              void* d_out, int out_size)
{
    const float* x    = (const float*)d_in[0];
    const float* wqkv = (const float*)d_in[1];
    const float* wo   = (const float*)d_in[2];
    float* out = (float*)d_out;

    float *qkvp, *Sp;
    __nv_bfloat16 *xh, *xl, *wqh, *wql, *woh, *wol;
    __nv_bfloat16 *qhh, *qhl, *khh, *khl, *ath, *atl;
    cudaGetSymbolAddress((void**)&qkvp, g_qkv);
    cudaGetSymbolAddress((void**)&Sp,   g_S);
    cudaGetSymbolAddress((void**)&xh,   g_xh);
    cudaGetSymbolAddress((void**)&xl,   g_xl);
    cudaGetSymbolAddress((void**)&wqh,  g_wqh);
    cudaGetSymbolAddress((void**)&wql,  g_wql);
    cudaGetSymbolAddress((void**)&woh,  g_woh);
    cudaGetSymbolAddress((void**)&wol,  g_wol);
    cudaGetSymbolAddress((void**)&qhh,  g_qhh);
    cudaGetSymbolAddress((void**)&qhl,  g_qhl);
    cudaGetSymbolAddress((void**)&khh,  g_khh);
    cudaGetSymbolAddress((void**)&khl,  g_khl);
    cudaGetSymbolAddress((void**)&ath,  g_ath);
    cudaGetSymbolAddress((void**)&atl,  g_atl);

    const int SMEM_G = 2048 + 2 * 65536;   // 133120
    const int SMEM_P = 2048 + 2 * 49152;   // 100352
    cudaFuncSetAttribute(gemm_tc, cudaFuncAttributeMaxDynamicSharedMemorySize, SMEM_G);
    cudaFuncSetAttribute(pv_tc,   cudaFuncAttributeMaxDynamicSharedMemorySize, SMEM_P);

    // conversions
    split_kernel<<<(BATCH * SEQ * DIM / 4 + 255) / 256, 256>>>((const float4*)x, xh, xl,
                                                               BATCH * SEQ * DIM / 4);
    transpose_split_kernel<<<dim3(TDIM / 32, DIM / 32), dim3(32, 8)>>>(wqkv, wqh, wql, DIM, TDIM);
    transpose_split_kernel<<<dim3(DIM / 32, DIM / 32), dim3(32, 8)>>>(wo, woh, wol, DIM, DIM);

    // QKV projection: [8192,1024] @ [1024,3072]
    gemm_tc<<<dim3(TDIM / 128, (BATCH * SEQ) / 128, 1), 256, SMEM_G>>>(
        xh, xl, wqh, wql, qkvp, DIM, DIM, DIM, TDIM, 0, 0, 0, 1.0f);

    conv_qk_kernel<<<(1 << 21) / 256, 256>>>();
    conv_vt_kernel<<<dim3(SEQ / 64, BATCH * HEADS), 256>>>();

    for (int b = 0; b < BATCH; b++) {
        const long long qo = (long long)b * HEADS * SEQ * 64;
        // scores: per head 2048x2048, K=64, scale 1/8
        gemm_tc<<<dim3(SEQ / 128, SEQ / 128, HEADS), 256, SMEM_G>>>(
            qhh + qo, qhl + qo, khh + qo, khl + qo, Sp,
            64, 64, 64, SEQ,
            (long long)SEQ * 64, (long long)SEQ * 64, (long long)SEQ * SEQ, 0.125f);
        stats_kernel<<<(SEQ * SEQ) / 256, 256>>>();
        pv_tc<<<dim3(SEQ / 128, HEADS), 256, SMEM_P>>>(b);
    }

    // output projection: [8192,1024] @ [1024,1024]
    gemm_tc<<<dim3(DIM / 128, (BATCH * SEQ) / 128, 1), 256, SMEM_G>>>(
        ath, atl, woh, wol, out, DIM, DIM, DIM, DIM, 0, 0, 0, 1.0f);
}

// round 11
// speedup vs baseline: 2.2881x; 1.3281x over previous
#include <cuda_runtime.h>
#include <cuda_bf16.h>
#include <stdint.h>

#define BATCH 4
#define SEQ   2048
#define DIM   1024
#define HEADS 16
#define TDIM  3072

#if !defined(__CUDA_ARCH__)
#define TC_OK 0
#elif defined(__CUDA_ARCH_FEAT_SM103_ALL) || defined(__CUDA_ARCH_FEAT_SM100_ALL) || \
      defined(__CUDA_ARCH_SPECIFIC__) || defined(__CUDA_ARCH_FAMILY_SPECIFIC__)
#define TC_OK 1
#else
#define TC_OK 0
#endif

// ---------------- scratch ----------------
__device__ __align__(256) float g_qkv[BATCH * SEQ * TDIM];
__device__ __align__(256) float g_S[(size_t)HEADS * SEQ * SEQ];     // per-batch reuse
__device__ __align__(256) __nv_bfloat16 g_Ph[(size_t)HEADS * SEQ * SEQ];  // softmax probs hi
__device__ __align__(256) __nv_bfloat16 g_Pl[(size_t)HEADS * SEQ * SEQ];  // softmax probs lo
__device__ __align__(256) __nv_bfloat16 g_xh[BATCH * SEQ * DIM];
__device__ __align__(256) __nv_bfloat16 g_xl[BATCH * SEQ * DIM];
__device__ __align__(256) __nv_bfloat16 g_wqh[TDIM * DIM];
__device__ __align__(256) __nv_bfloat16 g_wql[TDIM * DIM];
__device__ __align__(256) __nv_bfloat16 g_woh[DIM * DIM];
__device__ __align__(256) __nv_bfloat16 g_wol[DIM * DIM];
__device__ __align__(256) __nv_bfloat16 g_qhh[BATCH * HEADS * SEQ * 64];
__device__ __align__(256) __nv_bfloat16 g_qhl[BATCH * HEADS * SEQ * 64];
__device__ __align__(256) __nv_bfloat16 g_khh[BATCH * HEADS * SEQ * 64];
__device__ __align__(256) __nv_bfloat16 g_khl[BATCH * HEADS * SEQ * 64];
__device__ __align__(256) __nv_bfloat16 g_vth[BATCH * HEADS * 64 * SEQ];
__device__ __align__(256) __nv_bfloat16 g_vtl[BATCH * HEADS * 64 * SEQ];
__device__ __align__(256) __nv_bfloat16 g_ath[BATCH * SEQ * DIM];
__device__ __align__(256) __nv_bfloat16 g_atl[BATCH * SEQ * DIM];

// ---------------- PTX helpers ----------------
__device__ __forceinline__ uint32_t smem_u32(const void* p) {
    return (uint32_t)__cvta_generic_to_shared(p);
}
__device__ __forceinline__ uint32_t elect_one() {
    uint32_t pred;
    asm volatile("{\n\t.reg .pred p;\n\telect.sync _|p, 0xFFFFFFFF;\n\tselp.b32 %0, 1, 0, p;\n\t}"
                 : "=r"(pred));
    return pred;
}
#define MBAR_INIT(a, c) \
    asm volatile("mbarrier.init.shared.b64 [%0], %1;" :: "r"(a), "r"(c) : "memory")
#define MBAR_WAIT(addr, par) do {                                               \
    uint32_t _m = (addr), _p = (par), _d;                                       \
    asm volatile("{\n\t.reg .pred p;\n\t"                                       \
        "mbarrier.try_wait.parity.acquire.cta.shared::cta.b64 p, [%1], %2;\n\t" \
        "selp.b32 %0, 1, 0, p;\n\t}" : "=r"(_d) : "r"(_m), "r"(_p) : "memory"); \
    if (!_d) {                                                                  \
        asm volatile("{\n\t.reg .pred P1;\n\t"                                  \
        "WL_%=:\n\t"                                                            \
        "mbarrier.try_wait.parity.acquire.cta.shared::cta.b64 P1, [%0], %1, 0x989680;\n\t" \
        "@P1 bra.uni WD_%=;\n\tbra.uni WL_%=;\n\tWD_%=:\n\t}"                   \
        :: "r"(_m), "r"(_p) : "memory");                                        \
    }                                                                           \
} while (0)
#define TC_ALLOC(sa, n) \
    asm volatile("tcgen05.alloc.cta_group::1.sync.aligned.shared::cta.b32 [%0], %1;" :: "r"(sa), "r"(n) : "memory")
#define TC_DEALLOC(t, n) \
    asm volatile("tcgen05.dealloc.cta_group::1.sync.aligned.b32 %0, %1;" :: "r"(t), "r"(n))
#define TC_RELINQ() \
    asm volatile("tcgen05.relinquish_alloc_permit.cta_group::1.sync.aligned;")
#define TC_COMMIT(a) \
    asm volatile("tcgen05.commit.cta_group::1.mbarrier::arrive::one.shared::cluster.b64 [%0];" :: "r"(a) : "memory")
#define TC_FENCE_AFTER()  asm volatile("tcgen05.fence::after_thread_sync;" ::: "memory")
#define TC_WAIT_LD()      asm volatile("tcgen05.wait::ld.sync.aligned;" ::: "memory")
#define FENCE_ASYNC()     asm volatile("fence.proxy.async.shared::cta;" ::: "memory")

// cp.async (sm_80+; legal in plain compute_103 pass)
#define CP_ASYNC16(dst, src) \
    asm volatile("cp.async.cg.shared.global [%0], [%1], 16;" :: "r"(dst), "l"(src) : "memory")
#define CP_COMMIT() asm volatile("cp.async.commit_group;" ::: "memory")
#define CP_WAIT(n)  asm volatile("cp.async.wait_group %0;" :: "n"(n) : "memory")

#define TC_LD_X32(r, a) \
    asm volatile( \
        "tcgen05.ld.sync.aligned.32x32b.x32.b32 " \
        "{%0, %1, %2, %3, %4, %5, %6, %7, %8, %9, %10, %11, %12, %13, %14, %15, " \
        " %16, %17, %18, %19, %20, %21, %22, %23, %24, %25, %26, %27, %28, %29, %30, %31}, [%32];" \
        : "=r"((r)[0]),  "=r"((r)[1]),  "=r"((r)[2]),  "=r"((r)[3]), \
          "=r"((r)[4]),  "=r"((r)[5]),  "=r"((r)[6]),  "=r"((r)[7]), \
          "=r"((r)[8]),  "=r"((r)[9]),  "=r"((r)[10]), "=r"((r)[11]), \
          "=r"((r)[12]), "=r"((r)[13]), "=r"((r)[14]), "=r"((r)[15]), \
          "=r"((r)[16]), "=r"((r)[17]), "=r"((r)[18]), "=r"((r)[19]), \
          "=r"((r)[20]), "=r"((r)[21]), "=r"((r)[22]), "=r"((r)[23]), \
          "=r"((r)[24]), "=r"((r)[25]), "=r"((r)[26]), "=r"((r)[27]), \
          "=r"((r)[28]), "=r"((r)[29]), "=r"((r)[30]), "=r"((r)[31]) \
        : "r"(a))

#define SWZ(x) ((x) ^ (((x) >> 3) & 0x70))

__device__ __forceinline__ uint64_t make_desc(uint32_t addr) {
    const uint64_t base =
        (uint64_t(2) << 61) | (uint64_t(1) << 46) | (uint64_t(64) << 32) | (uint64_t(1) << 16);
    return base | ((addr >> 4) & 0x3FFF);
}
#if defined(__CUDA_ARCH__) && TC_OK
__device__ __forceinline__ void mma_bf16(uint32_t d, uint64_t ad, uint64_t bd,
                                         uint32_t idesc, uint32_t en) {
    asm volatile(
        "{\n\t.reg .pred p;\n\tsetp.ne.u32 p, %5, 0;\n\t"
        "tcgen05.mma.cta_group::1.kind::f16 [%0], %1, %2, %3, {%4, %4, %4, %4}, p;\n\t}"
        :: "r"(d), "l"(ad), "l"(bd), "r"(idesc), "r"(0u), "r"(en) : "memory");
}
#endif

// hi/lo bf16 split of a float4 -> two packed uint2 (4 bf16 each)
__device__ __forceinline__ void split4(float4 p, uint2& hv, uint2& lv) {
    __nv_bfloat16 h0 = __float2bfloat16(p.x), h1 = __float2bfloat16(p.y);
    __nv_bfloat16 h2 = __float2bfloat16(p.z), h3 = __float2bfloat16(p.w);
    __nv_bfloat16 l0 = __float2bfloat16(p.x - __bfloat162float(h0));
    __nv_bfloat16 l1 = __float2bfloat16(p.y - __bfloat162float(h1));
    __nv_bfloat16 l2 = __float2bfloat16(p.z - __bfloat162float(h2));
    __nv_bfloat16 l3 = __float2bfloat16(p.w - __bfloat162float(h3));
    __nv_bfloat162 a, b, c, d;
    a.x = h0; a.y = h1; b.x = h2; b.y = h3;
    c.x = l0; c.y = l1; d.x = l2; d.y = l3;
    hv.x = *(uint32_t*)&a; hv.y = *(uint32_t*)&b;
    lv.x = *(uint32_t*)&c; lv.y = *(uint32_t*)&d;
}

// ---------------- conversion kernels ----------------
__global__ void __launch_bounds__(256) split_kernel(const float4* __restrict__ src,
                                                    __nv_bfloat16* __restrict__ hi,
                                                    __nv_bfloat16* __restrict__ lo, int n4) {
    int i = blockIdx.x * 256 + threadIdx.x;
    if (i >= n4) return;
    uint2 hv, lv;
    split4(src[i], hv, lv);
    *(uint2*)(hi + (size_t)i * 4) = hv;
    *(uint2*)(lo + (size_t)i * 4) = lv;
}

__global__ void __launch_bounds__(256) transpose_split_kernel(
    const float* __restrict__ W, __nv_bfloat16* __restrict__ Th,
    __nv_bfloat16* __restrict__ Tl, int K, int N) {
    __shared__ float t[32][33];
    const int n0 = blockIdx.x * 32, k0 = blockIdx.y * 32;
    const int tx = threadIdx.x, ty = threadIdx.y;
    #pragma unroll
    for (int j = 0; j < 32; j += 8)
        t[ty + j][tx] = W[(size_t)(k0 + ty + j) * N + n0 + tx];
    __syncthreads();
    #pragma unroll
    for (int j = 0; j < 32; j += 8) {
        float v = t[tx][ty + j];
        size_t o = (size_t)(n0 + ty + j) * K + k0 + tx;
        __nv_bfloat16 h = __float2bfloat16(v);
        Th[o] = h;
        Tl[o] = __float2bfloat16(v - __bfloat162float(h));
    }
}

__global__ void __launch_bounds__(256) conv_qk_kernel() {
    int i4 = blockIdx.x * 256 + threadIdx.x;
    int k4 = i4 & 15;
    int l  = (i4 >> 4) & 2047;
    int h  = (i4 >> 15) & 15;
    int b  = i4 >> 19;
    const float* row = g_qkv + (size_t)b * SEQ * TDIM
                     + (size_t)(h * 128 + (l >> 4)) * TDIM + (l & 15) * 64 + k4 * 4;
    size_t o = (size_t)i4 * 4;
    uint2 hv, lv;
    split4(*(const float4*)row, hv, lv);
    *(uint2*)(g_qhh + o) = hv; *(uint2*)(g_qhl + o) = lv;
    split4(*(const float4*)(row + 1024), hv, lv);
    *(uint2*)(g_khh + o) = hv; *(uint2*)(g_khl + o) = lv;
}

__global__ void __launch_bounds__(256) conv_vt_kernel() {
    __shared__ float t[64][65];
    const int z = blockIdx.y;
    const int b = z >> 4, h = z & 15;
    const int m0 = blockIdx.x * 64;
    const int tid = threadIdx.x;
    for (int idx = tid; idx < 1024; idx += 256) {
        int r = idx >> 4, c4 = idx & 15;
        int m = m0 + r;
        const float* row = g_qkv + (size_t)b * SEQ * TDIM
                         + (size_t)(h * 128 + (m >> 4)) * TDIM + (m & 15) * 64 + 2048 + c4 * 4;
        float4 v = *(const float4*)row;
        t[r][c4 * 4 + 0] = v.x; t[r][c4 * 4 + 1] = v.y;
        t[r][c4 * 4 + 2] = v.z; t[r][c4 * 4 + 3] = v.w;
    }
    __syncthreads();
    for (int idx = tid; idx < 1024; idx += 256) {
        int kk = idx >> 4, c4 = idx & 15;
        float4 v;
        v.x = t[c4 * 4 + 0][kk]; v.y = t[c4 * 4 + 1][kk];
        v.z = t[c4 * 4 + 2][kk]; v.w = t[c4 * 4 + 3][kk];
        size_t o = ((size_t)z * 64 + kk) * SEQ + m0 + c4 * 4;
        uint2 hv, lv;
        split4(v, hv, lv);
        *(uint2*)(g_vth + o) = hv;
        *(uint2*)(g_vtl + o) = lv;
    }
}

// ---------------- tcgen05 bf16x3 GEMM (128x128 tile), cp.async pipelined ----------------
__global__ void __launch_bounds__(256, 1) gemm_tc(
    const __nv_bfloat16* __restrict__ Ah, const __nv_bfloat16* __restrict__ Al,
    const __nv_bfloat16* __restrict__ Bh, const __nv_bfloat16* __restrict__ Bl,
    float* __restrict__ C, int K, int ldA, int ldB, int ldC,
    long long sAz, long long sBz, long long sCz, float scale)
{
    extern __shared__ char dsm[];
    uint32_t raw = smem_u32(dsm);
    uint32_t sbase = (raw + 1023) & ~1023u;
    const int tid = threadIdx.x, wid = tid >> 5, lid = tid & 31;
    const int z = blockIdx.z;
    const int row0 = blockIdx.y * 128, col0 = blockIdx.x * 128;
    Ah += (size_t)z * sAz; Al += (size_t)z * sAz;
    Bh += (size_t)z * sBz; Bl += (size_t)z * sBz;
    C  += (size_t)z * sCz;
#if TC_OK
    const uint32_t MB0 = sbase + 8, MB1 = sbase + 16;
    const int STAGE = 65536;

    if (wid == 0) {
        if (elect_one()) { MBAR_INIT(MB0, 1); MBAR_INIT(MB1, 1); }
        TC_ALLOC(sbase, 128);
        TC_RELINQ();
    }
    __syncthreads();
    uint32_t tmem;
    asm volatile("ld.shared.b32 %0, [%1];" : "=r"(tmem) : "r"(sbase));

    const uint32_t IDESC = (1u << 4) | (1u << 7) | (1u << 10) | (16u << 17) | (8u << 24);
    const int T = K >> 6;
    const int lr = tid >> 1;                 // load row pair base: 128 rows, 2 thr/row
    const int lc = (tid & 1) * 4;            // 4 chunks of 16B each half-row

    // per-tile cp.async load (A/B hi/lo, 64KB total)
    auto load_tile = [&](int t, int buf) {
        uint32_t sb = sbase + 1024 + buf * STAGE;
        const int k0 = t * 64;
        #pragma unroll
        for (int c = 0; c < 4; ++c) {
            int cc = lc + c;
            size_t ao = (size_t)(row0 + lr) * ldA + k0 + cc * 8;
            size_t bo = (size_t)(col0 + lr) * ldB + k0 + cc * 8;
            uint32_t off = SWZ(lr * 128 + cc * 16);
            CP_ASYNC16(sb + off,         Ah + ao);
            CP_ASYNC16(sb + 16384 + off, Al + ao);
            CP_ASYNC16(sb + 32768 + off, Bh + bo);
            CP_ASYNC16(sb + 49152 + off, Bl + bo);
        }
    };

    uint32_t ph[2] = {0, 0};
    load_tile(0, 0); CP_COMMIT();
    for (int t = 0; t < T; ++t) {
        const int buf = t & 1;
        if (t + 1 < T) {
            const int nb = (t + 1) & 1;
            if (t >= 1) { MBAR_WAIT(nb ? MB1 : MB0, ph[nb]); ph[nb] ^= 1; }
            load_tile(t + 1, nb); CP_COMMIT();
            CP_WAIT(1);
        } else {
            CP_WAIT(0);
        }
        __syncthreads();
        if (wid == 0) {
            FENCE_ASYNC();
            if (elect_one()) {
                uint32_t sb = sbase + 1024 + buf * STAGE;
                uint64_t dah = make_desc(sb), dal = make_desc(sb + 16384);
                uint64_t dbh = make_desc(sb + 32768), dbl = make_desc(sb + 49152);
                #pragma unroll
                for (int ks = 0; ks < 4; ++ks) {
                    mma_bf16(tmem, dah + ks * 2, dbh + ks * 2, IDESC, (uint32_t)((t | ks) != 0));
                    mma_bf16(tmem, dah + ks * 2, dbl + ks * 2, IDESC, 1u);
                    mma_bf16(tmem, dal + ks * 2, dbh + ks * 2, IDESC, 1u);
                }
                TC_COMMIT(buf ? MB1 : MB0);
            }
        }
    }
    MBAR_WAIT(MB0, ph[0]);
    if (T >= 2) MBAR_WAIT(MB1, ph[1]);
    TC_FENCE_AFTER();
    if (wid < 4) {
        const int row = row0 + wid * 32 + lid;
        float* cp = C + (size_t)row * ldC + col0;
        for (int c0 = 0; c0 < 128; c0 += 32) {
            uint32_t r[32];
            TC_LD_X32(r, tmem + c0);
            TC_WAIT_LD();
            #pragma unroll
            for (int j = 0; j < 32; j += 4) {
                float4 o;
                o.x = __uint_as_float(r[j + 0]) * scale;
                o.y = __uint_as_float(r[j + 1]) * scale;
                o.z = __uint_as_float(r[j + 2]) * scale;
                o.w = __uint_as_float(r[j + 3]) * scale;
                *(float4*)&cp[c0 + j] = o;
            }
        }
    }
    __syncthreads();
    if (wid == 0) TC_DEALLOC(tmem, 128);
#else
    // FFMA fallback (compute_103 PTX pass only)
    char* sp = dsm + (sbase - raw);
    float* As = (float*)sp;
    float* Bs = As + 16 * 132;
    const int ty = tid >> 4, tx = tid & 15;
    float acc[8][8];
    #pragma unroll
    for (int i = 0; i < 8; i++)
        #pragma unroll
        for (int j = 0; j < 8; j++) acc[i][j] = 0.0f;
    for (int k0 = 0; k0 < K; k0 += 16) {
        for (int idx = tid; idx < 2048; idx += 256) {
            int r = idx >> 4, c = idx & 15;
            size_t ao = (size_t)(row0 + r) * ldA + k0 + c;
            size_t bo = (size_t)(col0 + r) * ldB + k0 + c;
            As[c * 132 + r] = __bfloat162float(Ah[ao]) + __bfloat162float(Al[ao]);
            Bs[c * 132 + r] = __bfloat162float(Bh[bo]) + __bfloat162float(Bl[bo]);
        }
        __syncthreads();
        #pragma unroll
        for (int k = 0; k < 16; k++) {
            float a[8], bb[8];
            #pragma unroll
            for (int i = 0; i < 8; i++) a[i]  = As[k * 132 + ty * 8 + i];
            #pragma unroll
            for (int j = 0; j < 8; j++) bb[j] = Bs[k * 132 + tx * 8 + j];
            #pragma unroll
            for (int i = 0; i < 8; i++)
                #pragma unroll
                for (int j = 0; j < 8; j++)
                    acc[i][j] = fmaf(a[i], bb[j], acc[i][j]);
        }
        __syncthreads();
    }
    #pragma unroll
    for (int i = 0; i < 8; i++)
        #pragma unroll
        for (int j = 0; j < 8; j++)
            C[(size_t)(row0 + ty * 8 + i) * ldC + col0 + tx * 8 + j] = acc[i][j] * scale;
#endif
}

// ---------------- stats: softmax over heads -> P hi/lo bf16 planes ----------------
// one thread handles 2 consecutive lm positions (vectorized 2-wide)
__global__ void __launch_bounds__(256) stats_kernel() {
    const size_t lm = ((size_t)blockIdx.x * 256 + threadIdx.x) * 2;
    float2 s[HEADS];
    #pragma unroll
    for (int h = 0; h < HEADS; h++)
        s[h] = *(const float2*)(g_S + (size_t)h * SEQ * SEQ + lm);
    float mx0 = s[0].x, mx1 = s[0].y;
    #pragma unroll
    for (int h = 1; h < HEADS; h++) {
        mx0 = fmaxf(mx0, s[h].x);
        mx1 = fmaxf(mx1, s[h].y);
    }
    float e0[HEADS], e1[HEADS];
    float z0 = 0.0f, z1 = 0.0f;
    #pragma unroll
    for (int h = 0; h < HEADS; h++) {
        e0[h] = __expf(s[h].x - mx0); z0 += e0[h];
        e1[h] = __expf(s[h].y - mx1); z1 += e1[h];
    }
    const float r0 = __frcp_rn(z0), r1 = __frcp_rn(z1);
    #pragma unroll
    for (int h = 0; h < HEADS; h++) {
        float p0 = e0[h] * r0, p1 = e1[h] * r1;
        __nv_bfloat16 h0 = __float2bfloat16(p0), h1 = __float2bfloat16(p1);
        __nv_bfloat16 l0 = __float2bfloat16(p0 - __bfloat162float(h0));
        __nv_bfloat16 l1 = __float2bfloat16(p1 - __bfloat162float(h1));
        __nv_bfloat162 hp, lp;
        hp.x = h0; hp.y = h1; lp.x = l0; lp.y = l1;
        *(uint32_t*)(g_Ph + (size_t)h * SEQ * SEQ + lm) = *(uint32_t*)&hp;
        *(uint32_t*)(g_Pl + (size_t)h * SEQ * SEQ + lm) = *(uint32_t*)&lp;
    }
}

// ---------------- PV: P(bf16 hi/lo) @ V^T, N=64, cp.async pipelined ----------------
__global__ void __launch_bounds__(256, 1) pv_tc(int b)
{
    extern __shared__ char dsm[];
    uint32_t raw = smem_u32(dsm);
    uint32_t sbase = (raw + 1023) & ~1023u;
    const int tid = threadIdx.x, wid = tid >> 5, lid = tid & 31;
    const int h = blockIdx.y, l0 = blockIdx.x * 128;
    const __nv_bfloat16* Php = g_Ph + (size_t)h * SEQ * SEQ;
    const __nv_bfloat16* Plp = g_Pl + (size_t)h * SEQ * SEQ;
    const __nv_bfloat16* Vhp = g_vth + (size_t)((b * HEADS + h) * 64) * SEQ;
    const __nv_bfloat16* Vlp = g_vtl + (size_t)((b * HEADS + h) * 64) * SEQ;
#if TC_OK
    const uint32_t MB0 = sbase + 8, MB1 = sbase + 16;
    const int STAGE = 49152;   // Ph 16K, Pl 16K, Vh 8K, Vl 8K

    if (wid == 0) {
        if (elect_one()) { MBAR_INIT(MB0, 1); MBAR_INIT(MB1, 1); }
        TC_ALLOC(sbase, 64);
        TC_RELINQ();
    }
    __syncthreads();
    uint32_t tmem;
    asm volatile("ld.shared.b32 %0, [%1];" : "=r"(tmem) : "r"(sbase));

    const uint32_t IDESC = (1u << 4) | (1u << 7) | (1u << 10) | (8u << 17) | (8u << 24);
    const int T = 32;
    const int lr = tid >> 1;               // P: 128 rows, 2 thr/row
    const int lc = (tid & 1) * 4;
    const int vr = tid >> 2;               // V: 64 rows, 4 thr/row
    const int vc = (tid & 3) * 2;

    auto load_tile = [&](int t, int buf) {
        uint32_t sb = sbase + 1024 + buf * STAGE;
        const int m0 = t * 64;
        #pragma unroll
        for (int c = 0; c < 4; ++c) {
            int cc = lc + c;
            size_t po = (size_t)(l0 + lr) * SEQ + m0 + cc * 8;
            uint32_t off = SWZ(lr * 128 + cc * 16);
            CP_ASYNC16(sb + off,         Php + po);
            CP_ASYNC16(sb + 16384 + off, Plp + po);
        }
        #pragma unroll
        for (int c = 0; c < 2; ++c) {
            int cc = vc + c;
            size_t vo = (size_t)vr * SEQ + m0 + cc * 8;
            uint32_t off = SWZ(vr * 128 + cc * 16);
            CP_ASYNC16(sb + 32768 + off, Vhp + vo);
            CP_ASYNC16(sb + 40960 + off, Vlp + vo);
        }
    };

    uint32_t ph[2] = {0, 0};
    load_tile(0, 0); CP_COMMIT();
    for (int t = 0; t < T; ++t) {
        const int buf = t & 1;
        if (t + 1 < T) {
            const int nb = (t + 1) & 1;
            if (t >= 1) { MBAR_WAIT(nb ? MB1 : MB0, ph[nb]); ph[nb] ^= 1; }
            load_tile(t + 1, nb); CP_COMMIT();
            CP_WAIT(1);
        } else {
            CP_WAIT(0);
        }
        __syncthreads();
        if (wid == 0) {
            FENCE_ASYNC();
            if (elect_one()) {
                uint32_t sb = sbase + 1024 + buf * STAGE;
                uint64_t dph = make_desc(sb), dpl = make_desc(sb + 16384);
                uint64_t dvh = make_desc(sb + 32768), dvl = make_desc(sb + 40960);
                #pragma unroll
                for (int ks = 0; ks < 4; ++ks) {
                    mma_bf16(tmem, dph + ks * 2, dvh + ks * 2, IDESC, (uint32_t)((t | ks) != 0));
                    mma_bf16(tmem, dph + ks * 2, dvl + ks * 2, IDESC, 1u);
                    mma_bf16(tmem, dpl + ks * 2, dvh + ks * 2, IDESC, 1u);
                }
                TC_COMMIT(buf ? MB1 : MB0);
            }
        }
    }
    MBAR_WAIT(MB0, ph[0]);
    MBAR_WAIT(MB1, ph[1]);
    TC_FENCE_AFTER();
    if (wid < 4) {
        const int row = l0 + wid * 32 + lid;
        __nv_bfloat16* oh = g_ath + (size_t)(b * SEQ + row) * DIM + h * 64;
        __nv_bfloat16* ol = g_atl + (size_t)(b * SEQ + row) * DIM + h * 64;
        for (int c0 = 0; c0 < 64; c0 += 32) {
            uint32_t r[32];
            TC_LD_X32(r, tmem + c0);
            TC_WAIT_LD();
            #pragma unroll
            for (int j = 0; j < 32; j += 4) {
                float4 v;
                v.x = __uint_as_float(r[j + 0]); v.y = __uint_as_float(r[j + 1]);
                v.z = __uint_as_float(r[j + 2]); v.w = __uint_as_float(r[j + 3]);
                uint2 hv, lv;
                split4(v, hv, lv);
                *(uint2*)(oh + c0 + j) = hv;
                *(uint2*)(ol + c0 + j) = lv;
            }
        }
    }
    __syncthreads();
    if (wid == 0) TC_DEALLOC(tmem, 64);
#else
    // FFMA fallback
    char* sp = dsm + (sbase - raw);
    float* Ps = (float*)sp;                  // [16][132]
    float* Vs = Ps + 16 * 132;               // [16][72]
    const int ty = tid >> 3;
    const int tx = tid & 7;
    float acc[4][8];
    #pragma unroll
    for (int i = 0; i < 4; i++)
        #pragma unroll
        for (int j = 0; j < 8; j++) acc[i][j] = 0.0f;
    for (int m0 = 0; m0 < SEQ; m0 += 16) {
        for (int idx = tid; idx < 2048; idx += 256) {
            int m = idx >> 7, l = idx & 127;
            size_t po = (size_t)(l0 + l) * SEQ + m0 + m;
            Ps[m * 132 + l] = __bfloat162float(Php[po]) + __bfloat162float(Plp[po]);
        }
        for (int idx = tid; idx < 1024; idx += 256) {
            int m = idx >> 6, k = idx & 63;
            size_t vo = (size_t)k * SEQ + m0 + m;
            Vs[m * 72 + k] = __bfloat162float(Vhp[vo]) + __bfloat162float(Vlp[vo]);
        }
        __syncthreads();
        #pragma unroll
        for (int m = 0; m < 16; m++) {
            float a[4], bb[8];
            #pragma unroll
            for (int i = 0; i < 4; i++) a[i]  = Ps[m * 132 + ty * 4 + i];
            #pragma unroll
            for (int j = 0; j < 8; j++) bb[j] = Vs[m * 72 + tx * 8 + j];
            #pragma unroll
            for (int i = 0; i < 4; i++)
                #pragma unroll
                for (int j = 0; j < 8; j++)
                    acc[i][j] = fmaf(a[i], bb[j], acc[i][j]);
        }
        __syncthreads();
    }
    #pragma unroll
    for (int i = 0; i < 4; i++) {
        int row = l0 + ty * 4 + i;
        __nv_bfloat16* oh = g_ath + (size_t)(b * SEQ + row) * DIM + h * 64 + tx * 8;
        __nv_bfloat16* ol = g_atl + (size_t)(b * SEQ + row) * DIM + h * 64 + tx * 8;
        float4 v0 = make_float4(acc[i][0], acc[i][1], acc[i][2], acc[i][3]);
        float4 v1 = make_float4(acc[i][4], acc[i][5], acc[i][6], acc[i][7]);
        uint2 hv, lv;
        split4(v0, hv, lv);
        *(uint2*)oh = hv; *(uint2*)ol = lv;
        split4(v1, hv, lv);
        *(uint2*)(oh + 4) = hv; *(uint2*)(ol + 4) = lv;
    }
#endif
}

// ---------------- launch ----------------
extern "C" void kernel_launch(void* const* d_in, const int* in_sizes, int n_in,
                              void* d_out, int out_size)
{
    const float* x    = (const float*)d_in[0];
    const float* wqkv = (const float*)d_in[1];
    const float* wo   = (const float*)d_in[2];
    float* out = (float*)d_out;

    float *qkvp, *Sp;
    __nv_bfloat16 *xh, *xl, *wqh, *wql, *woh, *wol;
    __nv_bfloat16 *qhh, *qhl, *khh, *khl, *ath, *atl;
    cudaGetSymbolAddress((void**)&qkvp, g_qkv);
    cudaGetSymbolAddress((void**)&Sp,   g_S);
    cudaGetSymbolAddress((void**)&xh,   g_xh);
    cudaGetSymbolAddress((void**)&xl,   g_xl);
    cudaGetSymbolAddress((void**)&wqh,  g_wqh);
    cudaGetSymbolAddress((void**)&wql,  g_wql);
    cudaGetSymbolAddress((void**)&woh,  g_woh);
    cudaGetSymbolAddress((void**)&wol,  g_wol);
    cudaGetSymbolAddress((void**)&qhh,  g_qhh);
    cudaGetSymbolAddress((void**)&qhl,  g_qhl);
    cudaGetSymbolAddress((void**)&khh,  g_khh);
    cudaGetSymbolAddress((void**)&khl,  g_khl);
    cudaGetSymbolAddress((void**)&ath,  g_ath);
    cudaGetSymbolAddress((void**)&atl,  g_atl);

    const int SMEM_G = 2048 + 2 * 65536;   // 133120
    const int SMEM_P = 2048 + 2 * 49152;   // 100352
    cudaFuncSetAttribute(gemm_tc, cudaFuncAttributeMaxDynamicSharedMemorySize, SMEM_G);
    cudaFuncSetAttribute(pv_tc,   cudaFuncAttributeMaxDynamicSharedMemorySize, SMEM_P);

    split_kernel<<<(BATCH * SEQ * DIM / 4 + 255) / 256, 256>>>((const float4*)x, xh, xl,
                                                               BATCH * SEQ * DIM / 4);
    transpose_split_kernel<<<dim3(TDIM / 32, DIM / 32), dim3(32, 8)>>>(wqkv, wqh, wql, DIM, TDIM);
    transpose_split_kernel<<<dim3(DIM / 32, DIM / 32), dim3(32, 8)>>>(wo, woh, wol, DIM, DIM);

    gemm_tc<<<dim3(TDIM / 128, (BATCH * SEQ) / 128, 1), 256, SMEM_G>>>(
        xh, xl, wqh, wql, qkvp, DIM, DIM, DIM, TDIM, 0, 0, 0, 1.0f);

    conv_qk_kernel<<<(1 << 21) / 256, 256>>>();
    conv_vt_kernel<<<dim3(SEQ / 64, BATCH * HEADS), 256>>>();

    for (int b = 0; b < BATCH; b++) {
        const long long qo = (long long)b * HEADS * SEQ * 64;
        gemm_tc<<<dim3(SEQ / 128, SEQ / 128, HEADS), 256, SMEM_G>>>(
            qhh + qo, qhl + qo, khh + qo, khl + qo, Sp,
            64, 64, 64, SEQ,
            (long long)SEQ * 64, (long long)SEQ * 64, (long long)SEQ * SEQ, 0.125f);
        stats_kernel<<<(SEQ * SEQ / 2) / 256, 256>>>();
        pv_tc<<<dim3(SEQ / 128, HEADS), 256, SMEM_P>>>(b);
    }

    gemm_tc<<<dim3(DIM / 128, (BATCH * SEQ) / 128, 1), 256, SMEM_G>>>(
        ath, atl, woh, wol, out, DIM, DIM, DIM, DIM, 0, 0, 0, 1.0f);
}

// round 12
// speedup vs baseline: 2.3443x; 1.0245x over previous
#include <cuda_runtime.h>
#include <cuda_bf16.h>
#include <stdint.h>

#define BATCH 4
#define SEQ   2048
#define DIM   1024
#define HEADS 16
#define TDIM  3072

#if !defined(__CUDA_ARCH__)
#define TC_OK 0
#elif defined(__CUDA_ARCH_FEAT_SM103_ALL) || defined(__CUDA_ARCH_FEAT_SM100_ALL) || \
      defined(__CUDA_ARCH_SPECIFIC__) || defined(__CUDA_ARCH_FAMILY_SPECIFIC__)
#define TC_OK 1
#else
#define TC_OK 0
#endif

// ---------------- scratch (full-batch) ----------------
__device__ __align__(256) float g_qkv[BATCH * SEQ * TDIM];
__device__ __align__(256) float g_S[(size_t)BATCH * HEADS * SEQ * SEQ];        // 1.07 GB
__device__ __align__(256) __nv_bfloat16 g_Ph[(size_t)BATCH * HEADS * SEQ * SEQ]; // 536 MB
__device__ __align__(256) __nv_bfloat16 g_Pl[(size_t)BATCH * HEADS * SEQ * SEQ]; // 536 MB
__device__ __align__(256) __nv_bfloat16 g_xh[BATCH * SEQ * DIM];
__device__ __align__(256) __nv_bfloat16 g_xl[BATCH * SEQ * DIM];
__device__ __align__(256) __nv_bfloat16 g_wqh[TDIM * DIM];
__device__ __align__(256) __nv_bfloat16 g_wql[TDIM * DIM];
__device__ __align__(256) __nv_bfloat16 g_woh[DIM * DIM];
__device__ __align__(256) __nv_bfloat16 g_wol[DIM * DIM];
__device__ __align__(256) __nv_bfloat16 g_qhh[BATCH * HEADS * SEQ * 64];
__device__ __align__(256) __nv_bfloat16 g_qhl[BATCH * HEADS * SEQ * 64];
__device__ __align__(256) __nv_bfloat16 g_khh[BATCH * HEADS * SEQ * 64];
__device__ __align__(256) __nv_bfloat16 g_khl[BATCH * HEADS * SEQ * 64];
__device__ __align__(256) __nv_bfloat16 g_vth[BATCH * HEADS * 64 * SEQ];
__device__ __align__(256) __nv_bfloat16 g_vtl[BATCH * HEADS * 64 * SEQ];
__device__ __align__(256) __nv_bfloat16 g_ath[BATCH * SEQ * DIM];
__device__ __align__(256) __nv_bfloat16 g_atl[BATCH * SEQ * DIM];

// ---------------- PTX helpers ----------------
__device__ __forceinline__ uint32_t smem_u32(const void* p) {
    return (uint32_t)__cvta_generic_to_shared(p);
}
__device__ __forceinline__ uint32_t elect_one() {
    uint32_t pred;
    asm volatile("{\n\t.reg .pred p;\n\telect.sync _|p, 0xFFFFFFFF;\n\tselp.b32 %0, 1, 0, p;\n\t}"
                 : "=r"(pred));
    return pred;
}
#define MBAR_INIT(a, c) \
    asm volatile("mbarrier.init.shared.b64 [%0], %1;" :: "r"(a), "r"(c) : "memory")
#define MBAR_WAIT(addr, par) do {                                               \
    uint32_t _m = (addr), _p = (par), _d;                                       \
    asm volatile("{\n\t.reg .pred p;\n\t"                                       \
        "mbarrier.try_wait.parity.acquire.cta.shared::cta.b64 p, [%1], %2;\n\t" \
        "selp.b32 %0, 1, 0, p;\n\t}" : "=r"(_d) : "r"(_m), "r"(_p) : "memory"); \
    if (!_d) {                                                                  \
        asm volatile("{\n\t.reg .pred P1;\n\t"                                  \
        "WL_%=:\n\t"                                                            \
        "mbarrier.try_wait.parity.acquire.cta.shared::cta.b64 P1, [%0], %1, 0x989680;\n\t" \
        "@P1 bra.uni WD_%=;\n\tbra.uni WL_%=;\n\tWD_%=:\n\t}"                   \
        :: "r"(_m), "r"(_p) : "memory");                                        \
    }                                                                           \
} while (0)
#define TC_ALLOC(sa, n) \
    asm volatile("tcgen05.alloc.cta_group::1.sync.aligned.shared::cta.b32 [%0], %1;" :: "r"(sa), "r"(n) : "memory")
#define TC_DEALLOC(t, n) \
    asm volatile("tcgen05.dealloc.cta_group::1.sync.aligned.b32 %0, %1;" :: "r"(t), "r"(n))
#define TC_RELINQ() \
    asm volatile("tcgen05.relinquish_alloc_permit.cta_group::1.sync.aligned;")
#define TC_COMMIT(a) \
    asm volatile("tcgen05.commit.cta_group::1.mbarrier::arrive::one.shared::cluster.b64 [%0];" :: "r"(a) : "memory")
#define TC_FENCE_AFTER()  asm volatile("tcgen05.fence::after_thread_sync;" ::: "memory")
#define TC_WAIT_LD()      asm volatile("tcgen05.wait::ld.sync.aligned;" ::: "memory")
#define FENCE_ASYNC()     asm volatile("fence.proxy.async.shared::cta;" ::: "memory")

#define CP_ASYNC16(dst, src) \
    asm volatile("cp.async.cg.shared.global [%0], [%1], 16;" :: "r"(dst), "l"(src) : "memory")
#define CP_COMMIT() asm volatile("cp.async.commit_group;" ::: "memory")
#define CP_WAIT(n)  asm volatile("cp.async.wait_group %0;" :: "n"(n) : "memory")

#define TC_LD_X32(r, a) \
    asm volatile( \
        "tcgen05.ld.sync.aligned.32x32b.x32.b32 " \
        "{%0, %1, %2, %3, %4, %5, %6, %7, %8, %9, %10, %11, %12, %13, %14, %15, " \
        " %16, %17, %18, %19, %20, %21, %22, %23, %24, %25, %26, %27, %28, %29, %30, %31}, [%32];" \
        : "=r"((r)[0]),  "=r"((r)[1]),  "=r"((r)[2]),  "=r"((r)[3]), \
          "=r"((r)[4]),  "=r"((r)[5]),  "=r"((r)[6]),  "=r"((r)[7]), \
          "=r"((r)[8]),  "=r"((r)[9]),  "=r"((r)[10]), "=r"((r)[11]), \
          "=r"((r)[12]), "=r"((r)[13]), "=r"((r)[14]), "=r"((r)[15]), \
          "=r"((r)[16]), "=r"((r)[17]), "=r"((r)[18]), "=r"((r)[19]), \
          "=r"((r)[20]), "=r"((r)[21]), "=r"((r)[22]), "=r"((r)[23]), \
          "=r"((r)[24]), "=r"((r)[25]), "=r"((r)[26]), "=r"((r)[27]), \
          "=r"((r)[28]), "=r"((r)[29]), "=r"((r)[30]), "=r"((r)[31]) \
        : "r"(a))

#define SWZ(x) ((x) ^ (((x) >> 3) & 0x70))

__device__ __forceinline__ uint64_t make_desc(uint32_t addr) {
    const uint64_t base =
        (uint64_t(2) << 61) | (uint64_t(1) << 46) | (uint64_t(64) << 32) | (uint64_t(1) << 16);
    return base | ((addr >> 4) & 0x3FFF);
}
#if defined(__CUDA_ARCH__) && TC_OK
__device__ __forceinline__ void mma_bf16(uint32_t d, uint64_t ad, uint64_t bd,
                                         uint32_t idesc, uint32_t en) {
    asm volatile(
        "{\n\t.reg .pred p;\n\tsetp.ne.u32 p, %5, 0;\n\t"
        "tcgen05.mma.cta_group::1.kind::f16 [%0], %1, %2, %3, {%4, %4, %4, %4}, p;\n\t}"
        :: "r"(d), "l"(ad), "l"(bd), "r"(idesc), "r"(0u), "r"(en) : "memory");
}
#endif

__device__ __forceinline__ void split4(float4 p, uint2& hv, uint2& lv) {
    __nv_bfloat16 h0 = __float2bfloat16(p.x), h1 = __float2bfloat16(p.y);
    __nv_bfloat16 h2 = __float2bfloat16(p.z), h3 = __float2bfloat16(p.w);
    __nv_bfloat16 l0 = __float2bfloat16(p.x - __bfloat162float(h0));
    __nv_bfloat16 l1 = __float2bfloat16(p.y - __bfloat162float(h1));
    __nv_bfloat16 l2 = __float2bfloat16(p.z - __bfloat162float(h2));
    __nv_bfloat16 l3 = __float2bfloat16(p.w - __bfloat162float(h3));
    __nv_bfloat162 a, b, c, d;
    a.x = h0; a.y = h1; b.x = h2; b.y = h3;
    c.x = l0; c.y = l1; d.x = l2; d.y = l3;
    hv.x = *(uint32_t*)&a; hv.y = *(uint32_t*)&b;
    lv.x = *(uint32_t*)&c; lv.y = *(uint32_t*)&d;
}

// ---------------- conversion kernels ----------------
__global__ void __launch_bounds__(256) split_kernel(const float4* __restrict__ src,
                                                    __nv_bfloat16* __restrict__ hi,
                                                    __nv_bfloat16* __restrict__ lo, int n4) {
    int i = blockIdx.x * 256 + threadIdx.x;
    if (i >= n4) return;
    uint2 hv, lv;
    split4(src[i], hv, lv);
    *(uint2*)(hi + (size_t)i * 4) = hv;
    *(uint2*)(lo + (size_t)i * 4) = lv;
}

__global__ void __launch_bounds__(256) transpose_split_kernel(
    const float* __restrict__ W, __nv_bfloat16* __restrict__ Th,
    __nv_bfloat16* __restrict__ Tl, int K, int N) {
    __shared__ float t[32][33];
    const int n0 = blockIdx.x * 32, k0 = blockIdx.y * 32;
    const int tx = threadIdx.x, ty = threadIdx.y;
    #pragma unroll
    for (int j = 0; j < 32; j += 8)
        t[ty + j][tx] = W[(size_t)(k0 + ty + j) * N + n0 + tx];
    __syncthreads();
    #pragma unroll
    for (int j = 0; j < 32; j += 8) {
        float v = t[tx][ty + j];
        size_t o = (size_t)(n0 + ty + j) * K + k0 + tx;
        __nv_bfloat16 h = __float2bfloat16(v);
        Th[o] = h;
        Tl[o] = __float2bfloat16(v - __bfloat162float(h));
    }
}

__global__ void __launch_bounds__(256) conv_qk_kernel() {
    int i4 = blockIdx.x * 256 + threadIdx.x;
    int k4 = i4 & 15;
    int l  = (i4 >> 4) & 2047;
    int h  = (i4 >> 15) & 15;
    int b  = i4 >> 19;
    const float* row = g_qkv + (size_t)b * SEQ * TDIM
                     + (size_t)(h * 128 + (l >> 4)) * TDIM + (l & 15) * 64 + k4 * 4;
    size_t o = (size_t)i4 * 4;
    uint2 hv, lv;
    split4(*(const float4*)row, hv, lv);
    *(uint2*)(g_qhh + o) = hv; *(uint2*)(g_qhl + o) = lv;
    split4(*(const float4*)(row + 1024), hv, lv);
    *(uint2*)(g_khh + o) = hv; *(uint2*)(g_khl + o) = lv;
}

__global__ void __launch_bounds__(256) conv_vt_kernel() {
    __shared__ float t[64][65];
    const int z = blockIdx.y;
    const int b = z >> 4, h = z & 15;
    const int m0 = blockIdx.x * 64;
    const int tid = threadIdx.x;
    for (int idx = tid; idx < 1024; idx += 256) {
        int r = idx >> 4, c4 = idx & 15;
        int m = m0 + r;
        const float* row = g_qkv + (size_t)b * SEQ * TDIM
                         + (size_t)(h * 128 + (m >> 4)) * TDIM + (m & 15) * 64 + 2048 + c4 * 4;
        float4 v = *(const float4*)row;
        t[r][c4 * 4 + 0] = v.x; t[r][c4 * 4 + 1] = v.y;
        t[r][c4 * 4 + 2] = v.z; t[r][c4 * 4 + 3] = v.w;
    }
    __syncthreads();
    for (int idx = tid; idx < 1024; idx += 256) {
        int kk = idx >> 4, c4 = idx & 15;
        float4 v;
        v.x = t[c4 * 4 + 0][kk]; v.y = t[c4 * 4 + 1][kk];
        v.z = t[c4 * 4 + 2][kk]; v.w = t[c4 * 4 + 3][kk];
        size_t o = ((size_t)z * 64 + kk) * SEQ + m0 + c4 * 4;
        uint2 hv, lv;
        split4(v, hv, lv);
        *(uint2*)(g_vth + o) = hv;
        *(uint2*)(g_vtl + o) = lv;
    }
}

// ---------------- tcgen05 bf16x3 GEMM, 3-stage cp.async pipeline ----------------
__global__ void __launch_bounds__(256, 1) gemm_tc(
    const __nv_bfloat16* __restrict__ Ah, const __nv_bfloat16* __restrict__ Al,
    const __nv_bfloat16* __restrict__ Bh, const __nv_bfloat16* __restrict__ Bl,
    float* __restrict__ C, int K, int ldA, int ldB, int ldC,
    long long sAz, long long sBz, long long sCz, float scale)
{
    extern __shared__ char dsm[];
    uint32_t raw = smem_u32(dsm);
    uint32_t sbase = (raw + 1023) & ~1023u;
    const int tid = threadIdx.x, wid = tid >> 5, lid = tid & 31;
    const int z = blockIdx.z;
    const int row0 = blockIdx.y * 128, col0 = blockIdx.x * 128;
    Ah += (size_t)z * sAz; Al += (size_t)z * sAz;
    Bh += (size_t)z * sBz; Bl += (size_t)z * sBz;
    C  += (size_t)z * sCz;
#if TC_OK
    const int STAGE = 65536;
    uint32_t MBarr[3] = {sbase + 8, sbase + 16, sbase + 24};

    if (wid == 0) {
        if (elect_one()) { MBAR_INIT(MBarr[0], 1); MBAR_INIT(MBarr[1], 1); MBAR_INIT(MBarr[2], 1); }
        TC_ALLOC(sbase, 128);
        TC_RELINQ();
    }
    __syncthreads();
    uint32_t tmem;
    asm volatile("ld.shared.b32 %0, [%1];" : "=r"(tmem) : "r"(sbase));

    const uint32_t IDESC = (1u << 4) | (1u << 7) | (1u << 10) | (16u << 17) | (8u << 24);
    const int T = K >> 6;
    const int lr = tid >> 1;
    const int lc = (tid & 1) * 4;

    auto load_tile = [&](int t, int buf) {
        uint32_t sb = sbase + 1024 + buf * STAGE;
        const int k0 = t * 64;
        #pragma unroll
        for (int c = 0; c < 4; ++c) {
            int cc = lc + c;
            size_t ao = (size_t)(row0 + lr) * ldA + k0 + cc * 8;
            size_t bo = (size_t)(col0 + lr) * ldB + k0 + cc * 8;
            uint32_t off = SWZ(lr * 128 + cc * 16);
            CP_ASYNC16(sb + off,         Ah + ao);
            CP_ASYNC16(sb + 16384 + off, Al + ao);
            CP_ASYNC16(sb + 32768 + off, Bh + bo);
            CP_ASYNC16(sb + 49152 + off, Bl + bo);
        }
    };

    uint32_t ph[3] = {0, 0, 0};
    load_tile(0, 0); CP_COMMIT();
    if (T > 1) { load_tile(1, 1); CP_COMMIT(); }
    for (int t = 0; t < T; ++t) {
        const int s = t % 3;
        if (t + 2 < T) {
            const int ns = (t + 2) % 3;
            if (t >= 1) { MBAR_WAIT(MBarr[ns], ph[ns]); ph[ns] ^= 1; }
            load_tile(t + 2, ns); CP_COMMIT();
        }
        if (t + 2 < T)      { CP_WAIT(2); }
        else if (t + 1 < T) { CP_WAIT(1); }
        else                { CP_WAIT(0); }
        __syncthreads();
        if (wid == 0) {
            FENCE_ASYNC();
            if (elect_one()) {
                uint32_t sb = sbase + 1024 + s * STAGE;
                uint64_t dah = make_desc(sb), dal = make_desc(sb + 16384);
                uint64_t dbh = make_desc(sb + 32768), dbl = make_desc(sb + 49152);
                #pragma unroll
                for (int ks = 0; ks < 4; ++ks) {
                    mma_bf16(tmem, dah + ks * 2, dbh + ks * 2, IDESC, (uint32_t)((t | ks) != 0));
                    mma_bf16(tmem, dah + ks * 2, dbl + ks * 2, IDESC, 1u);
                    mma_bf16(tmem, dal + ks * 2, dbh + ks * 2, IDESC, 1u);
                }
                TC_COMMIT(MBarr[s]);
            }
        }
    }
    {
        const int nst = T < 3 ? T : 3;
        for (int s = 0; s < nst; ++s) { MBAR_WAIT(MBarr[s], ph[s]); }
    }
    TC_FENCE_AFTER();
    if (wid < 4) {
        const int row = row0 + wid * 32 + lid;
        float* cp = C + (size_t)row * ldC + col0;
        for (int c0 = 0; c0 < 128; c0 += 32) {
            uint32_t r[32];
            TC_LD_X32(r, tmem + c0);
            TC_WAIT_LD();
            #pragma unroll
            for (int j = 0; j < 32; j += 4) {
                float4 o;
                o.x = __uint_as_float(r[j + 0]) * scale;
                o.y = __uint_as_float(r[j + 1]) * scale;
                o.z = __uint_as_float(r[j + 2]) * scale;
                o.w = __uint_as_float(r[j + 3]) * scale;
                *(float4*)&cp[c0 + j] = o;
            }
        }
    }
    __syncthreads();
    if (wid == 0) TC_DEALLOC(tmem, 128);
#else
    // FFMA fallback (compute_103 PTX pass only)
    char* sp = dsm + (sbase - raw);
    float* As = (float*)sp;
    float* Bs = As + 16 * 132;
    const int ty = tid >> 4, tx = tid & 15;
    float acc[8][8];
    #pragma unroll
    for (int i = 0; i < 8; i++)
        #pragma unroll
        for (int j = 0; j < 8; j++) acc[i][j] = 0.0f;
    for (int k0 = 0; k0 < K; k0 += 16) {
        for (int idx = tid; idx < 2048; idx += 256) {
            int r = idx >> 4, c = idx & 15;
            size_t ao = (size_t)(row0 + r) * ldA + k0 + c;
            size_t bo = (size_t)(col0 + r) * ldB + k0 + c;
            As[c * 132 + r] = __bfloat162float(Ah[ao]) + __bfloat162float(Al[ao]);
            Bs[c * 132 + r] = __bfloat162float(Bh[bo]) + __bfloat162float(Bl[bo]);
        }
        __syncthreads();
        #pragma unroll
        for (int k = 0; k < 16; k++) {
            float a[8], bb[8];
            #pragma unroll
            for (int i = 0; i < 8; i++) a[i]  = As[k * 132 + ty * 8 + i];
            #pragma unroll
            for (int j = 0; j < 8; j++) bb[j] = Bs[k * 132 + tx * 8 + j];
            #pragma unroll
            for (int i = 0; i < 8; i++)
                #pragma unroll
                for (int j = 0; j < 8; j++)
                    acc[i][j] = fmaf(a[i], bb[j], acc[i][j]);
        }
        __syncthreads();
    }
    #pragma unroll
    for (int i = 0; i < 8; i++)
        #pragma unroll
        for (int j = 0; j < 8; j++)
            C[(size_t)(row0 + ty * 8 + i) * ldC + col0 + tx * 8 + j] = acc[i][j] * scale;
#endif
}

// ---------------- stats: softmax over heads -> P hi/lo (all batches) ----------------
__global__ void __launch_bounds__(256) stats_kernel() {
    const size_t lm2 = ((size_t)blockIdx.x * 256 + threadIdx.x) * 2;
    const int b = (int)(lm2 >> 22);                    // / (SEQ*SEQ)
    const size_t lm = lm2 & ((size_t)SEQ * SEQ - 1);
    const size_t base = (size_t)b * HEADS * SEQ * SEQ + lm;
    float2 s[HEADS];
    #pragma unroll
    for (int h = 0; h < HEADS; h++)
        s[h] = *(const float2*)(g_S + base + (size_t)h * SEQ * SEQ);
    float mx0 = s[0].x, mx1 = s[0].y;
    #pragma unroll
    for (int h = 1; h < HEADS; h++) {
        mx0 = fmaxf(mx0, s[h].x);
        mx1 = fmaxf(mx1, s[h].y);
    }
    float e0[HEADS], e1[HEADS];
    float z0 = 0.0f, z1 = 0.0f;
    #pragma unroll
    for (int h = 0; h < HEADS; h++) {
        e0[h] = __expf(s[h].x - mx0); z0 += e0[h];
        e1[h] = __expf(s[h].y - mx1); z1 += e1[h];
    }
    const float r0 = __frcp_rn(z0), r1 = __frcp_rn(z1);
    #pragma unroll
    for (int h = 0; h < HEADS; h++) {
        float p0 = e0[h] * r0, p1 = e1[h] * r1;
        __nv_bfloat16 h0 = __float2bfloat16(p0), h1 = __float2bfloat16(p1);
        __nv_bfloat16 l0 = __float2bfloat16(p0 - __bfloat162float(h0));
        __nv_bfloat16 l1 = __float2bfloat16(p1 - __bfloat162float(h1));
        __nv_bfloat162 hp, lp;
        hp.x = h0; hp.y = h1; lp.x = l0; lp.y = l1;
        *(uint32_t*)(g_Ph + base + (size_t)h * SEQ * SEQ) = *(uint32_t*)&hp;
        *(uint32_t*)(g_Pl + base + (size_t)h * SEQ * SEQ) = *(uint32_t*)&lp;
    }
}

// ---------------- PV: P(bf16 hi/lo) @ V^T, 3-stage pipeline, all batches ----------------
__global__ void __launch_bounds__(256, 1) pv_tc()
{
    extern __shared__ char dsm[];
    uint32_t raw = smem_u32(dsm);
    uint32_t sbase = (raw + 1023) & ~1023u;
    const int tid = threadIdx.x, wid = tid >> 5, lid = tid & 31;
    const int z = blockIdx.y;                 // b*16+h
    const int b = z >> 4, h = z & 15;
    const int l0 = blockIdx.x * 128;
    const __nv_bfloat16* Php = g_Ph + (size_t)z * SEQ * SEQ;
    const __nv_bfloat16* Plp = g_Pl + (size_t)z * SEQ * SEQ;
    const __nv_bfloat16* Vhp = g_vth + (size_t)z * 64 * SEQ;
    const __nv_bfloat16* Vlp = g_vtl + (size_t)z * 64 * SEQ;
#if TC_OK
    const int STAGE = 49152;   // Ph 16K, Pl 16K, Vh 8K, Vl 8K
    uint32_t MBarr[3] = {sbase + 8, sbase + 16, sbase + 24};

    if (wid == 0) {
        if (elect_one()) { MBAR_INIT(MBarr[0], 1); MBAR_INIT(MBarr[1], 1); MBAR_INIT(MBarr[2], 1); }
        TC_ALLOC(sbase, 64);
        TC_RELINQ();
    }
    __syncthreads();
    uint32_t tmem;
    asm volatile("ld.shared.b32 %0, [%1];" : "=r"(tmem) : "r"(sbase));

    const uint32_t IDESC = (1u << 4) | (1u << 7) | (1u << 10) | (8u << 17) | (8u << 24);
    const int T = 32;
    const int lr = tid >> 1;
    const int lc = (tid & 1) * 4;
    const int vr = tid >> 2;
    const int vc = (tid & 3) * 2;

    auto load_tile = [&](int t, int buf) {
        uint32_t sb = sbase + 1024 + buf * STAGE;
        const int m0 = t * 64;
        #pragma unroll
        for (int c = 0; c < 4; ++c) {
            int cc = lc + c;
            size_t po = (size_t)(l0 + lr) * SEQ + m0 + cc * 8;
            uint32_t off = SWZ(lr * 128 + cc * 16);
            CP_ASYNC16(sb + off,         Php + po);
            CP_ASYNC16(sb + 16384 + off, Plp + po);
        }
        #pragma unroll
        for (int c = 0; c < 2; ++c) {
            int cc = vc + c;
            size_t vo = (size_t)vr * SEQ + m0 + cc * 8;
            uint32_t off = SWZ(vr * 128 + cc * 16);
            CP_ASYNC16(sb + 32768 + off, Vhp + vo);
            CP_ASYNC16(sb + 40960 + off, Vlp + vo);
        }
    };

    uint32_t ph[3] = {0, 0, 0};
    load_tile(0, 0); CP_COMMIT();
    load_tile(1, 1); CP_COMMIT();
    for (int t = 0; t < T; ++t) {
        const int s = t % 3;
        if (t + 2 < T) {
            const int ns = (t + 2) % 3;
            if (t >= 1) { MBAR_WAIT(MBarr[ns], ph[ns]); ph[ns] ^= 1; }
            load_tile(t + 2, ns); CP_COMMIT();
        }
        if (t + 2 < T)      { CP_WAIT(2); }
        else if (t + 1 < T) { CP_WAIT(1); }
        else                { CP_WAIT(0); }
        __syncthreads();
        if (wid == 0) {
            FENCE_ASYNC();
            if (elect_one()) {
                uint32_t sb = sbase + 1024 + s * STAGE;
                uint64_t dph = make_desc(sb), dpl = make_desc(sb + 16384);
                uint64_t dvh = make_desc(sb + 32768), dvl = make_desc(sb + 40960);
                #pragma unroll
                for (int ks = 0; ks < 4; ++ks) {
                    mma_bf16(tmem, dph + ks * 2, dvh + ks * 2, IDESC, (uint32_t)((t | ks) != 0));
                    mma_bf16(tmem, dph + ks * 2, dvl + ks * 2, IDESC, 1u);
                    mma_bf16(tmem, dpl + ks * 2, dvh + ks * 2, IDESC, 1u);
                }
                TC_COMMIT(MBarr[s]);
            }
        }
    }
    for (int s = 0; s < 3; ++s) { MBAR_WAIT(MBarr[s], ph[s]); }
    TC_FENCE_AFTER();
    if (wid < 4) {
        const int row = l0 + wid * 32 + lid;
        __nv_bfloat16* oh = g_ath + (size_t)(b * SEQ + row) * DIM + h * 64;
        __nv_bfloat16* ol = g_atl + (size_t)(b * SEQ + row) * DIM + h * 64;
        for (int c0 = 0; c0 < 64; c0 += 32) {
            uint32_t r[32];
            TC_LD_X32(r, tmem + c0);
            TC_WAIT_LD();
            #pragma unroll
            for (int j = 0; j < 32; j += 4) {
                float4 v;
                v.x = __uint_as_float(r[j + 0]); v.y = __uint_as_float(r[j + 1]);
                v.z = __uint_as_float(r[j + 2]); v.w = __uint_as_float(r[j + 3]);
                uint2 hv, lv;
                split4(v, hv, lv);
                *(uint2*)(oh + c0 + j) = hv;
                *(uint2*)(ol + c0 + j) = lv;
            }
        }
    }
    __syncthreads();
    if (wid == 0) TC_DEALLOC(tmem, 64);
#else
    // FFMA fallback
    char* sp = dsm + (sbase - raw);
    float* Ps = (float*)sp;
    float* Vs = Ps + 16 * 132;
    const int ty = tid >> 3;
    const int tx = tid & 7;
    float acc[4][8];
    #pragma unroll
    for (int i = 0; i < 4; i++)
        #pragma unroll
        for (int j = 0; j < 8; j++) acc[i][j] = 0.0f;
    for (int m0 = 0; m0 < SEQ; m0 += 16) {
        for (int idx = tid; idx < 2048; idx += 256) {
            int m = idx >> 7, l = idx & 127;
            size_t po = (size_t)(l0 + l) * SEQ + m0 + m;
            Ps[m * 132 + l] = __bfloat162float(Php[po]) + __bfloat162float(Plp[po]);
        }
        for (int idx = tid; idx < 1024; idx += 256) {
            int m = idx >> 6, k = idx & 63;
            size_t vo = (size_t)k * SEQ + m0 + m;
            Vs[m * 72 + k] = __bfloat162float(Vhp[vo]) + __bfloat162float(Vlp[vo]);
        }
        __syncthreads();
        #pragma unroll
        for (int m = 0; m < 16; m++) {
            float a[4], bb[8];
            #pragma unroll
            for (int i = 0; i < 4; i++) a[i]  = Ps[m * 132 + ty * 4 + i];
            #pragma unroll
            for (int j = 0; j < 8; j++) bb[j] = Vs[m * 72 + tx * 8 + j];
            #pragma unroll
            for (int i = 0; i < 4; i++)
                #pragma unroll
                for (int j = 0; j < 8; j++)
                    acc[i][j] = fmaf(a[i], bb[j], acc[i][j]);
        }
        __syncthreads();
    }
    #pragma unroll
    for (int i = 0; i < 4; i++) {
        int row = l0 + ty * 4 + i;
        __nv_bfloat16* oh = g_ath + (size_t)(b * SEQ + row) * DIM + h * 64 + tx * 8;
        __nv_bfloat16* ol = g_atl + (size_t)(b * SEQ + row) * DIM + h * 64 + tx * 8;
        float4 v0 = make_float4(acc[i][0], acc[i][1], acc[i][2], acc[i][3]);
        float4 v1 = make_float4(acc[i][4], acc[i][5], acc[i][6], acc[i][7]);
        uint2 hv, lv;
        split4(v0, hv, lv);
        *(uint2*)oh = hv; *(uint2*)ol = lv;
        split4(v1, hv, lv);
        *(uint2*)(oh + 4) = hv; *(uint2*)(ol + 4) = lv;
    }
#endif
}

// ---------------- launch ----------------
extern "C" void kernel_launch(void* const* d_in, const int* in_sizes, int n_in,
                              void* d_out, int out_size)
{
    const float* x    = (const float*)d_in[0];
    const float* wqkv = (const float*)d_in[1];
    const float* wo   = (const float*)d_in[2];
    float* out = (float*)d_out;

    float *qkvp, *Sp;
    __nv_bfloat16 *xh, *xl, *wqh, *wql, *woh, *wol;
    __nv_bfloat16 *qhh, *qhl, *khh, *khl, *ath, *atl;
    cudaGetSymbolAddress((void**)&qkvp, g_qkv);
    cudaGetSymbolAddress((void**)&Sp,   g_S);
    cudaGetSymbolAddress((void**)&xh,   g_xh);
    cudaGetSymbolAddress((void**)&xl,   g_xl);
    cudaGetSymbolAddress((void**)&wqh,  g_wqh);
    cudaGetSymbolAddress((void**)&wql,  g_wql);
    cudaGetSymbolAddress((void**)&woh,  g_woh);
    cudaGetSymbolAddress((void**)&wol,  g_wol);
    cudaGetSymbolAddress((void**)&qhh,  g_qhh);
    cudaGetSymbolAddress((void**)&qhl,  g_qhl);
    cudaGetSymbolAddress((void**)&khh,  g_khh);
    cudaGetSymbolAddress((void**)&khl,  g_khl);
    cudaGetSymbolAddress((void**)&ath,  g_ath);
    cudaGetSymbolAddress((void**)&atl,  g_atl);

    const int SMEM_G = 2048 + 3 * 65536;   // 198656
    const int SMEM_P = 2048 + 3 * 49152;   // 149504
    cudaFuncSetAttribute(gemm_tc, cudaFuncAttributeMaxDynamicSharedMemorySize, SMEM_G);
    cudaFuncSetAttribute(pv_tc,   cudaFuncAttributeMaxDynamicSharedMemorySize, SMEM_P);

    split_kernel<<<(BATCH * SEQ * DIM / 4 + 255) / 256, 256>>>((const float4*)x, xh, xl,
                                                               BATCH * SEQ * DIM / 4);
    transpose_split_kernel<<<dim3(TDIM / 32, DIM / 32), dim3(32, 8)>>>(wqkv, wqh, wql, DIM, TDIM);
    transpose_split_kernel<<<dim3(DIM / 32, DIM / 32), dim3(32, 8)>>>(wo, woh, wol, DIM, DIM);

    // QKV projection
    gemm_tc<<<dim3(TDIM / 128, (BATCH * SEQ) / 128, 1), 256, SMEM_G>>>(
        xh, xl, wqh, wql, qkvp, DIM, DIM, DIM, TDIM, 0, 0, 0, 1.0f);

    conv_qk_kernel<<<(1 << 21) / 256, 256>>>();
    conv_vt_kernel<<<dim3(SEQ / 64, BATCH * HEADS), 256>>>();

    // scores for ALL batches/heads in one launch (z = b*16+h)
    gemm_tc<<<dim3(SEQ / 128, SEQ / 128, BATCH * HEADS), 256, SMEM_G>>>(
        qhh, qhl, khh, khl, Sp,
        64, 64, 64, SEQ,
        (long long)SEQ * 64, (long long)SEQ * 64, (long long)SEQ * SEQ, 0.125f);

    // softmax-over-heads for all batches
    stats_kernel<<<(BATCH * SEQ * SEQ / 2) / 256, 256>>>();

    // PV for all batches/heads
    pv_tc<<<dim3(SEQ / 128, BATCH * HEADS), 256, SMEM_P>>>();

    // output projection
    gemm_tc<<<dim3(DIM / 128, (BATCH * SEQ) / 128, 1), 256, SMEM_G>>>(
        ath, atl, woh, wol, out, DIM, DIM, DIM, DIM, 0, 0, 0, 1.0f);
}